// round 6
// baseline (speedup 1.0000x reference)
#include <cuda_runtime.h>
#include <cuda_fp16.h>
#include <cstdint>

#define VOCABN 32000
#define EMBEDN 256
#define H1N    512
#define KVN    128
#define BN_    32
#define SN     512
#define TN     256
#define MROWS  (BN_*TN)   // 8192

// ---------------- scratch (static device globals; no allocation) ----------------
__device__ float  g_gates1[MROWS * 4 * H1N];     // fp32
__device__ float  g_gates2[MROWS * 4 * KVN];     // fp32
__device__ float  g_energy[MROWS * SN];          // fp32
__device__ __half g_Eh  [VOCABN * EMBEDN];
__device__ __half g_W1h [4 * H1N * EMBEDN];
__device__ __half g_W2h [4 * KVN * H1N];
__device__ __half g_keyh[BN_ * SN * KVN];
__device__ __half g_h1h [MROWS * H1N];
__device__ __half g_h2h [MROWS * KVN];
__device__ __half g_attnh[MROWS * SN];
__device__ __half g_valueTh[BN_ * KVN * SN];
__device__ __half g_outctxh[MROWS * EMBEDN];

// ---------------- helpers ----------------
__device__ __forceinline__ void cp16(void* dst_smem, const void* src) {
    unsigned s = (unsigned)__cvta_generic_to_shared(dst_smem);
    asm volatile("cp.async.cg.shared.global [%0], [%1], 16;" :: "r"(s), "l"(src));
}
__device__ __forceinline__ float sigf(float x) { return 1.f / (1.f + expf(-x)); }

// ---------------- fp32 -> fp16 convert ----------------
__global__ void conv_h4(const float4* __restrict__ src, uint2* __restrict__ dst, int n4)
{
    int i = blockIdx.x * blockDim.x + threadIdx.x;
    if (i < n4) {
        float4 v = src[i];
        __half2 h0 = __floats2half2_rn(v.x, v.y);
        __half2 h1 = __floats2half2_rn(v.z, v.w);
        uint2 o;
        o.x = *reinterpret_cast<unsigned*>(&h0);
        o.y = *reinterpret_cast<unsigned*>(&h1);
        dst[i] = o;
    }
}

#define LDH 40                 // halves per smem row: 32 data + 8 pad -> 80B stride

// =================================================================================
// BIG-TILE fp16 TN GEMM for K=256 stages (embed + logits). C = A @ B^T.
// CTA tile 128(m) x 256(n), BK=32, 8 warps (2m x 4n), warp tile 64x64.
// 3-stage cp.async pipeline, dynamic SMEM (3 * (128+256) * 40 halves = 92160 B).
// MODE 1: A rows gathered via token ids; plain fp32 store.
// MODE 3: logits epilogue (add bias[m]; store out[b][m][t], n = b*T + t).
// =================================================================================
#define BBM 128
#define BBN 256
#define BBK 32
#define ASTGH (BBM * LDH)        // 5120 halves
#define BSTGH (BBN * LDH)        // 10240 halves
#define STGH  (ASTGH + BSTGH)    // 15360 halves per stage
#define BIG_SMEM (3 * STGH * 2)  // 92160 bytes

template <int MODE>
__global__ void __launch_bounds__(256, 1)
gemm_big(const __half* __restrict__ A, const __half* __restrict__ Bmat,
         void* __restrict__ Cv,
         int K, int lda, int ldb, int ldc,
         const int* __restrict__ ytok,
         const float* __restrict__ bias)
{
    extern __shared__ __half sh[];

    const int tid  = threadIdx.x;
    const int warp = tid >> 5, lane = tid & 31;
    const int wm = warp >> 2, wn = warp & 3;
    const int g  = lane >> 2, tq = lane & 3;
    const int quad = lane >> 3, lr = lane & 7;
    const int bm0 = blockIdx.y * BBM;
    const int bn0 = blockIdx.x * BBN;

    // cp.async source pointers: A 512 chunks (2/thread), B 1024 chunks (4/thread)
    int rA[2], sA_[2];
    const __half* srcA[2];
#pragma unroll
    for (int i = 0; i < 2; i++) {
        int c = tid + i * 256;
        int r = c >> 2, seg = c & 3;
        rA[i] = r; sA_[i] = seg;
        if (MODE == 1) {
            int m   = bm0 + r;
            int tok = ((m & (TN - 1)) == 0) ? 0 : ytok[m - 1];
            srcA[i] = A + (long)tok * lda + seg * 8;
        } else {
            srcA[i] = A + (long)(bm0 + r) * lda + seg * 8;
        }
    }
    int rB[4], sB_[4];
    const __half* srcB[4];
#pragma unroll
    for (int i = 0; i < 4; i++) {
        int c = tid + i * 256;
        int r = c >> 2, seg = c & 3;
        rB[i] = r; sB_[i] = seg;
        srcB[i] = Bmat + (long)(bn0 + r) * ldb + seg * 8;
    }

    float acc[4][8][4];
#pragma unroll
    for (int i = 0; i < 4; i++)
#pragma unroll
        for (int j = 0; j < 8; j++)
#pragma unroll
            for (int q = 0; q < 4; q++) acc[i][j][q] = 0.f;

    const int nt = K / BBK;      // 8 for K=256

    // prologue: issue stages 0, 1
#pragma unroll
    for (int s = 0; s < 2; s++) {
        __half* Ad = sh + s * STGH;
        __half* Bd = Ad + ASTGH;
        int k0 = s * BBK;
#pragma unroll
        for (int i = 0; i < 2; i++)
            cp16(&Ad[rA[i] * LDH + sA_[i] * 8], srcA[i] + k0);
#pragma unroll
        for (int i = 0; i < 4; i++)
            cp16(&Bd[rB[i] * LDH + sB_[i] * 8], srcB[i] + k0);
        asm volatile("cp.async.commit_group;" ::: "memory");
    }

    int buf = 0;
    for (int kt = 0; kt < nt; kt++) {
        if (kt + 1 < nt) {
            asm volatile("cp.async.wait_group 1;" ::: "memory");
        } else {
            asm volatile("cp.async.wait_group 0;" ::: "memory");
        }
        __syncthreads();

        if (kt + 2 < nt) {
            int sb2 = (kt + 2) % 3;
            __half* Ad = sh + sb2 * STGH;
            __half* Bd = Ad + ASTGH;
            int k0 = (kt + 2) * BBK;
#pragma unroll
            for (int i = 0; i < 2; i++)
                cp16(&Ad[rA[i] * LDH + sA_[i] * 8], srcA[i] + k0);
#pragma unroll
            for (int i = 0; i < 4; i++)
                cp16(&Bd[rB[i] * LDH + sB_[i] * 8], srcB[i] + k0);
            asm volatile("cp.async.commit_group;" ::: "memory");
        }

        const __half* Asb = sh + buf * STGH;
        const __half* Bsb = Asb + ASTGH;

#pragma unroll
        for (int kk = 0; kk < BBK; kk += 16) {
            unsigned af[4][4], bf[8][2];
#pragma unroll
            for (int mi = 0; mi < 4; mi++) {
                int row = wm * 64 + mi * 16 + lr + (quad & 1) * 8;
                int col = kk + (quad >> 1) * 8;
                unsigned addr = (unsigned)__cvta_generic_to_shared(
                    &Asb[row * LDH + col]);
                asm volatile(
                    "ldmatrix.sync.aligned.m8n8.x4.shared.b16 {%0,%1,%2,%3}, [%4];"
                    : "=r"(af[mi][0]), "=r"(af[mi][1]),
                      "=r"(af[mi][2]), "=r"(af[mi][3]) : "r"(addr));
            }
#pragma unroll
            for (int np = 0; np < 4; np++) {
                int row = wn * 64 + np * 16 + lr + (quad & 1) * 8;
                int col = kk + (quad >> 1) * 8;
                unsigned addr = (unsigned)__cvta_generic_to_shared(
                    &Bsb[row * LDH + col]);
                unsigned r0, r1, r2, r3;
                asm volatile(
                    "ldmatrix.sync.aligned.m8n8.x4.shared.b16 {%0,%1,%2,%3}, [%4];"
                    : "=r"(r0), "=r"(r1), "=r"(r2), "=r"(r3) : "r"(addr));
                bf[2 * np + 0][0] = r0; bf[2 * np + 0][1] = r2;
                bf[2 * np + 1][0] = r1; bf[2 * np + 1][1] = r3;
            }
#pragma unroll
            for (int mi = 0; mi < 4; mi++)
#pragma unroll
                for (int ni = 0; ni < 8; ni++)
                    asm volatile(
                        "mma.sync.aligned.m16n8k16.row.col.f32.f16.f16.f32 "
                        "{%0,%1,%2,%3}, {%4,%5,%6,%7}, {%8,%9}, {%0,%1,%2,%3};\n"
                        : "+f"(acc[mi][ni][0]), "+f"(acc[mi][ni][1]),
                          "+f"(acc[mi][ni][2]), "+f"(acc[mi][ni][3])
                        : "r"(af[mi][0]), "r"(af[mi][1]),
                          "r"(af[mi][2]), "r"(af[mi][3]),
                          "r"(bf[ni][0]), "r"(bf[ni][1]));
        }
        buf = (buf + 1) % 3;
        __syncthreads();
    }

    // ---------------- epilogue ----------------
#pragma unroll
    for (int mi = 0; mi < 4; mi++) {
#pragma unroll
        for (int ni = 0; ni < 8; ni++) {
            int row = bm0 + wm * 64 + mi * 16 + g;
            int col = bn0 + wn * 64 + ni * 8 + 2 * tq;
#pragma unroll
            for (int rr = 0; rr < 2; rr++) {
                int r = row + rr * 8;
                float v0 = acc[mi][ni][rr * 2 + 0];
                float v1 = acc[mi][ni][rr * 2 + 1];
                if (MODE == 3) {
                    float bb = bias[r];
                    v0 += bb; v1 += bb;
                    int bidx = col >> 8;     // T = 256
                    int t    = col & 255;
                    *reinterpret_cast<float2*>(
                        (float*)Cv + (long)bidx * VOCABN * TN + (long)r * TN + t) =
                        make_float2(v0, v1);
                } else {
                    *reinterpret_cast<float2*>(
                        (float*)Cv + (long)r * ldc + col) = make_float2(v0, v1);
                }
            }
        }
    }
}

// ---------------- fp16 tiled TN GEMM (small stages; verified R5) ----------------
#define GBM 128
#define GBN 128
#define GBK 32
#define HSTG (128 * LDH)

template <int MODE, int OUTH>
__global__ void __launch_bounds__(256)
gemm_h(const __half* __restrict__ A, const __half* __restrict__ Bmat,
       void* __restrict__ Cv,
       int K, int lda, int ldb, int ldc,
       long sA, long sB, long sC,
       const int* __restrict__ enc_len)
{
    __shared__ __half As[2][HSTG];
    __shared__ __half Bs[2][HSTG];

    const int tid  = threadIdx.x;
    const int warp = tid >> 5, lane = tid & 31;
    const int wm = warp >> 2, wn = warp & 3;
    const int g  = lane >> 2, tq = lane & 3;
    const int quad = lane >> 3, lr = lane & 7;
    const int bm0 = blockIdx.y * GBM;
    const int bn0 = blockIdx.x * GBN;
    const int z   = blockIdx.z;

    const __half* Ab = A    + (long)z * sA;
    const __half* Bb = Bmat + (long)z * sB;

    int rowA[2], segA[2];
    const __half* srcA[2];
    const __half* srcB[2];
#pragma unroll
    for (int i = 0; i < 2; i++) {
        int c   = tid + i * 256;
        int r   = c >> 2;
        int seg = c & 3;
        rowA[i] = r; segA[i] = seg;
        srcA[i] = Ab + (long)(bm0 + r) * lda + seg * 8;
        srcB[i] = Bb + (long)(bn0 + r) * ldb + seg * 8;
    }

    float acc[4][4][4];
#pragma unroll
    for (int i = 0; i < 4; i++)
#pragma unroll
        for (int j = 0; j < 4; j++)
#pragma unroll
            for (int q = 0; q < 4; q++) acc[i][j][q] = 0.f;

    const int nt = K / GBK;

#pragma unroll
    for (int i = 0; i < 2; i++) {
        cp16(&As[0][rowA[i] * LDH + segA[i] * 8], srcA[i]);
        cp16(&Bs[0][rowA[i] * LDH + segA[i] * 8], srcB[i]);
    }
    asm volatile("cp.async.commit_group;" ::: "memory");

    for (int kt = 0; kt < nt; kt++) {
        if (kt + 1 < nt) {
            int k0 = (kt + 1) * GBK;
            int nb = (kt + 1) & 1;
#pragma unroll
            for (int i = 0; i < 2; i++) {
                cp16(&As[nb][rowA[i] * LDH + segA[i] * 8], srcA[i] + k0);
                cp16(&Bs[nb][rowA[i] * LDH + segA[i] * 8], srcB[i] + k0);
            }
            asm volatile("cp.async.commit_group;" ::: "memory");
            asm volatile("cp.async.wait_group 1;" ::: "memory");
        } else {
            asm volatile("cp.async.wait_group 0;" ::: "memory");
        }
        __syncthreads();

        const __half* Asb = As[kt & 1];
        const __half* Bsb = Bs[kt & 1];

#pragma unroll
        for (int kk = 0; kk < GBK; kk += 16) {
            unsigned af[4][4], bf[4][2];
#pragma unroll
            for (int mi = 0; mi < 4; mi++) {
                int row = wm * 64 + mi * 16 + lr + (quad & 1) * 8;
                int col = kk + (quad >> 1) * 8;
                unsigned addr = (unsigned)__cvta_generic_to_shared(
                    &Asb[row * LDH + col]);
                asm volatile(
                    "ldmatrix.sync.aligned.m8n8.x4.shared.b16 {%0,%1,%2,%3}, [%4];"
                    : "=r"(af[mi][0]), "=r"(af[mi][1]),
                      "=r"(af[mi][2]), "=r"(af[mi][3]) : "r"(addr));
            }
#pragma unroll
            for (int np = 0; np < 2; np++) {
                int row = wn * 32 + np * 16 + lr + (quad & 1) * 8;
                int col = kk + (quad >> 1) * 8;
                unsigned addr = (unsigned)__cvta_generic_to_shared(
                    &Bsb[row * LDH + col]);
                unsigned r0, r1, r2, r3;
                asm volatile(
                    "ldmatrix.sync.aligned.m8n8.x4.shared.b16 {%0,%1,%2,%3}, [%4];"
                    : "=r"(r0), "=r"(r1), "=r"(r2), "=r"(r3) : "r"(addr));
                bf[2 * np + 0][0] = r0; bf[2 * np + 0][1] = r2;
                bf[2 * np + 1][0] = r1; bf[2 * np + 1][1] = r3;
            }
#pragma unroll
            for (int mi = 0; mi < 4; mi++)
#pragma unroll
                for (int ni = 0; ni < 4; ni++)
                    asm volatile(
                        "mma.sync.aligned.m16n8k16.row.col.f32.f16.f16.f32 "
                        "{%0,%1,%2,%3}, {%4,%5,%6,%7}, {%8,%9}, {%0,%1,%2,%3};\n"
                        : "+f"(acc[mi][ni][0]), "+f"(acc[mi][ni][1]),
                          "+f"(acc[mi][ni][2]), "+f"(acc[mi][ni][3])
                        : "r"(af[mi][0]), "r"(af[mi][1]),
                          "r"(af[mi][2]), "r"(af[mi][3]),
                          "r"(bf[ni][0]), "r"(bf[ni][1]));
        }
        __syncthreads();
    }

#pragma unroll
    for (int mi = 0; mi < 4; mi++) {
#pragma unroll
        for (int ni = 0; ni < 4; ni++) {
            int row = bm0 + wm * 64 + mi * 16 + g;
            int col = bn0 + wn * 32 + ni * 8 + 2 * tq;
#pragma unroll
            for (int rr = 0; rr < 2; rr++) {
                int r = row + rr * 8;
                float v0 = acc[mi][ni][rr * 2 + 0];
                float v1 = acc[mi][ni][rr * 2 + 1];
                if (MODE == 2) {
                    int len = enc_len[z];
                    if (col     >= len) v0 = -1e9f;
                    if (col + 1 >= len) v1 = -1e9f;
                }
                if (OUTH) {
                    __half2 h = __floats2half2_rn(v0, v1);
                    *reinterpret_cast<__half2*>(
                        (__half*)Cv + (long)z * sC + (long)r * ldc + col) = h;
                } else {
                    *reinterpret_cast<float2*>(
                        (float*)Cv + (long)z * sC + (long)r * ldc + col) =
                        make_float2(v0, v1);
                }
            }
        }
    }
}

// ---------------- elementwise LSTM-cell activation (zero state), fp16 out --------
__global__ void act_lstm(const float* __restrict__ gates,
                         const float* __restrict__ b_ih,
                         const float* __restrict__ b_hh,
                         __half* __restrict__ h,
                         __half* __restrict__ hcopy, int H, int ldcopy, long total)
{
    long idx = (long)blockIdx.x * blockDim.x + threadIdx.x;
    if (idx >= total) return;
    int  j = (int)(idx & (H - 1));
    long m = idx / H;
    const float* gr = gates + m * 4 * H;
    float iv = gr[j]         + b_ih[j]         + b_hh[j];
    float gv = gr[2 * H + j] + b_ih[2 * H + j] + b_hh[2 * H + j];
    float ov = gr[3 * H + j] + b_ih[3 * H + j] + b_hh[3 * H + j];
    float c  = sigf(iv) * tanhf(gv);
    __half hv = __float2half_rn(sigf(ov) * tanhf(c));
    h[m * H + j] = hv;
    if (hcopy) hcopy[m * ldcopy + j] = hv;
}

// ---------------- per-row softmax over S=512: fp32 in, fp16 out ----------------
__global__ void softmax_rows(const float* __restrict__ e, __half* __restrict__ a)
{
    const int row = blockIdx.x;
    const float* p = e + (long)row * SN;
    __half* q = a + (long)row * SN;
    __shared__ float red[128];
    int tid = threadIdx.x;
    float v0 = p[tid], v1 = p[tid + 128], v2 = p[tid + 256], v3 = p[tid + 384];
    float mx = fmaxf(fmaxf(v0, v1), fmaxf(v2, v3));
    red[tid] = mx; __syncthreads();
    for (int st = 64; st > 0; st >>= 1) {
        if (tid < st) red[tid] = fmaxf(red[tid], red[tid + st]);
        __syncthreads();
    }
    mx = red[0]; __syncthreads();
    v0 = expf(v0 - mx); v1 = expf(v1 - mx); v2 = expf(v2 - mx); v3 = expf(v3 - mx);
    float s = v0 + v1 + v2 + v3;
    red[tid] = s; __syncthreads();
    for (int st = 64; st > 0; st >>= 1) {
        if (tid < st) red[tid] += red[tid + st];
        __syncthreads();
    }
    float inv = 1.f / red[0];
    q[tid]       = __float2half_rn(v0 * inv);
    q[tid + 128] = __float2half_rn(v1 * inv);
    q[tid + 256] = __float2half_rn(v2 * inv);
    q[tid + 384] = __float2half_rn(v3 * inv);
}

// ---------------- value transpose: (B,S,KV) fp32 -> (B,KV,S) fp16 ----------------
__global__ void transpose_v(const float* __restrict__ v, __half* __restrict__ vt)
{
    __shared__ float tile[32][33];
    int b  = blockIdx.z;
    int s0 = blockIdx.y * 32, v0 = blockIdx.x * 32;
    int x = threadIdx.x, y = threadIdx.y;
#pragma unroll
    for (int i = 0; i < 32; i += 8)
        tile[y + i][x] = v[((long)b * SN + s0 + y + i) * KVN + v0 + x];
    __syncthreads();
#pragma unroll
    for (int i = 0; i < 32; i += 8)
        vt[((long)b * KVN + v0 + y + i) * SN + s0 + x] = __float2half_rn(tile[x][y + i]);
}

// ---------------- launch ----------------
extern "C" void kernel_launch(void* const* d_in, const int* in_sizes, int n_in,
                              void* d_out, int out_size)
{
    const float* key   = (const float*)d_in[0];
    const float* value = (const float*)d_in[1];
    const int*   elen  = (const int*)  d_in[2];
    const int*   y     = (const int*)  d_in[3];
    const float* E     = (const float*)d_in[4];
    const float* W1    = (const float*)d_in[5];
    const float* bi1   = (const float*)d_in[6];
    const float* bh1   = (const float*)d_in[7];
    const float* W2    = (const float*)d_in[8];
    const float* bi2   = (const float*)d_in[9];
    const float* bh2   = (const float*)d_in[10];
    const float* bout  = (const float*)d_in[11];
    float*       out   = (float*)d_out;

    float  *gates1, *gates2, *energy;
    __half *Eh, *W1h, *W2h, *keyh, *h1h, *h2h, *attnh, *valueTh, *outctxh;
    cudaGetSymbolAddress((void**)&gates1, g_gates1);
    cudaGetSymbolAddress((void**)&gates2, g_gates2);
    cudaGetSymbolAddress((void**)&energy, g_energy);
    cudaGetSymbolAddress((void**)&Eh,     g_Eh);
    cudaGetSymbolAddress((void**)&W1h,    g_W1h);
    cudaGetSymbolAddress((void**)&W2h,    g_W2h);
    cudaGetSymbolAddress((void**)&keyh,   g_keyh);
    cudaGetSymbolAddress((void**)&h1h,    g_h1h);
    cudaGetSymbolAddress((void**)&h2h,    g_h2h);
    cudaGetSymbolAddress((void**)&attnh,  g_attnh);
    cudaGetSymbolAddress((void**)&valueTh,g_valueTh);
    cudaGetSymbolAddress((void**)&outctxh,g_outctxh);

    cudaFuncSetAttribute(gemm_big<1>, cudaFuncAttributeMaxDynamicSharedMemorySize, BIG_SMEM);
    cudaFuncSetAttribute(gemm_big<3>, cudaFuncAttributeMaxDynamicSharedMemorySize, BIG_SMEM);

    // 0) convert static GEMM operands to fp16
    conv_h4<<<(VOCABN * EMBEDN / 4 + 255) / 256, 256>>>((const float4*)E,  (uint2*)Eh,  VOCABN * EMBEDN / 4);
    conv_h4<<<(4 * H1N * EMBEDN / 4 + 255) / 256, 256>>>((const float4*)W1, (uint2*)W1h, 4 * H1N * EMBEDN / 4);
    conv_h4<<<(4 * KVN * H1N / 4 + 255) / 256, 256>>>((const float4*)W2, (uint2*)W2h, 4 * KVN * H1N / 4);
    conv_h4<<<(BN_ * SN * KVN / 4 + 255) / 256, 256>>>((const float4*)key,(uint2*)keyh, BN_ * SN * KVN / 4);

    // 1) gates1 = embed(tokens) @ W1^T     (M=8192, N=2048, K=256) fp32 out
    gemm_big<1><<<dim3(2048 / BBN, MROWS / BBM, 1), 256, BIG_SMEM>>>(
        Eh, W1h, gates1, EMBEDN, EMBEDN, EMBEDN, 4 * H1N, y, nullptr);

    // 2) h1 = lstm_act(gates1) -> fp16
    {
        long total = (long)MROWS * H1N;
        act_lstm<<<(unsigned)((total + 255) / 256), 256>>>(
            gates1, bi1, bh1, h1h, nullptr, H1N, 0, total);
    }

    // 3) gates2 = h1 @ W2^T                (M=8192, N=512, K=512) fp32 out
    gemm_h<0,0><<<dim3(512 / GBN, MROWS / GBM, 1), 256>>>(
        h1h, W2h, gates2, H1N, H1N, H1N, 4 * KVN,
        0, 0, 0, nullptr);

    // 4) h2 = lstm_act(gates2) -> fp16; copy into out_ctx[:, 0:128]
    {
        long total = (long)MROWS * KVN;
        act_lstm<<<(unsigned)((total + 255) / 256), 256>>>(
            gates2, bi2, bh2, h2h, outctxh, KVN, EMBEDN, total);
    }

    // 5) valueT (fp16)
    transpose_v<<<dim3(KVN / 32, SN / 32, BN_), dim3(32, 8)>>>(value, valueTh);

    // 6) energy[b,t,s] = h2 . key, masked  (per b: M=256, N=512, K=128) fp32 out
    gemm_h<2,0><<<dim3(SN / GBN, TN / GBM, BN_), 256>>>(
        h2h, keyh, energy, KVN, KVN, KVN, SN,
        (long)TN * KVN, (long)SN * KVN, (long)TN * SN, elen);

    // 7) softmax -> fp16 attn
    softmax_rows<<<MROWS, 128>>>(energy, attnh);

    // 8) context = attn @ valueT -> out_ctx[:, 128:256] fp16
    gemm_h<0,1><<<dim3(KVN / GBN, TN / GBM, BN_), 256>>>(
        attnh, valueTh, outctxh + KVN, SN, SN, SN, EMBEDN,
        (long)TN * SN, (long)KVN * SN, (long)TN * EMBEDN, nullptr);

    // 9) logits = E @ out_ctx^T + b_out -> out[b][v][t]  (M=32000, N=8192, K=256)
    gemm_big<3><<<dim3(MROWS / BBN, VOCABN / BBM, 1), 256, BIG_SMEM>>>(
        Eh, outctxh, out, EMBEDN, EMBEDN, EMBEDN, 0, nullptr, bout);

    (void)in_sizes; (void)n_in; (void)out_size;
}

// round 7
// speedup vs baseline: 1.2126x; 1.2126x over previous
#include <cuda_runtime.h>
#include <cuda_fp16.h>
#include <cstdint>

#define VOCABN 32000
#define EMBEDN 256
#define H1N    512
#define KVN    128
#define BN_    32
#define SN     512
#define TN     256
#define MROWS  (BN_*TN)   // 8192

// ---------------- scratch (static device globals; no allocation) ----------------
__device__ float  g_gates1[MROWS * 4 * H1N];     // fp32
__device__ float  g_gates2[MROWS * 4 * KVN];     // fp32
__device__ float  g_energy[MROWS * SN];          // fp32
__device__ __half g_Eh  [VOCABN * EMBEDN];
__device__ __half g_W1h [4 * H1N * EMBEDN];
__device__ __half g_W2h [4 * KVN * H1N];
__device__ __half g_keyh[BN_ * SN * KVN];
__device__ __half g_h1h [MROWS * H1N];
__device__ __half g_h2h [MROWS * KVN];
__device__ __half g_attnh[MROWS * SN];
__device__ __half g_valueTh[BN_ * KVN * SN];
__device__ __half g_outctxh[MROWS * EMBEDN];

// ---------------- helpers ----------------
__device__ __forceinline__ void cp16(void* dst_smem, const void* src) {
    unsigned s = (unsigned)__cvta_generic_to_shared(dst_smem);
    asm volatile("cp.async.cg.shared.global [%0], [%1], 16;" :: "r"(s), "l"(src));
}
__device__ __forceinline__ float sigf(float x) { return 1.f / (1.f + expf(-x)); }

// ---------------- fp32 -> fp16 convert ----------------
__global__ void conv_h4(const float4* __restrict__ src, uint2* __restrict__ dst, int n4)
{
    int i = blockIdx.x * blockDim.x + threadIdx.x;
    if (i < n4) {
        float4 v = src[i];
        __half2 h0 = __floats2half2_rn(v.x, v.y);
        __half2 h1 = __floats2half2_rn(v.z, v.w);
        uint2 o;
        o.x = *reinterpret_cast<unsigned*>(&h0);
        o.y = *reinterpret_cast<unsigned*>(&h1);
        dst[i] = o;
    }
}

// =================================================================================
// fp16 TN GEMM, CTA 128x128, BK=64, 3-stage cp.async, 8 warps (2m x 4n),
// warp tile 64x32 (acc = 64 regs/thread; 2 CTAs/SM).
// MODE 0: plain store  | MODE 1: token-gather A | MODE 2: energy mask
// MODE 3: logits (bias + (B,VOCAB,T) store)     | OUTH: fp16 output
// =================================================================================
#define GBM 128
#define GBN 128
#define GBK 64
#define LDH 72                  // halves per smem row: 64 data + 8 pad (144B stride)
#define TSTG (128 * LDH)        // halves per matrix per stage (9216)
#define STGH (2 * TSTG)         // halves per stage (A+B)
#define GSMEM (3 * STGH * 2)    // 110592 bytes

template <int MODE, int OUTH>
__global__ void __launch_bounds__(256, 2)
gemm_h(const __half* __restrict__ A, const __half* __restrict__ Bmat,
       void* __restrict__ Cv,
       int K, int lda, int ldb, int ldc,
       long sA, long sB, long sC,
       const int* __restrict__ ytok,
       const int* __restrict__ enc_len,
       const float* __restrict__ bias)
{
    extern __shared__ __half sh[];

    const int tid  = threadIdx.x;
    const int warp = tid >> 5, lane = tid & 31;
    const int wm = warp >> 2, wn = warp & 3;
    const int g  = lane >> 2, tq = lane & 3;
    const int quad = lane >> 3, lr = lane & 7;
    const int bm0 = blockIdx.y * GBM;
    const int bn0 = blockIdx.x * GBN;
    const int z   = blockIdx.z;

    const __half* Ab = A    + (long)z * sA;
    const __half* Bb = Bmat + (long)z * sB;

    // cp.async mapping: per matrix per stage 128 rows x 8 segs = 1024 chunks; 4/thread
    int rA[4], sA_[4];
    const __half* srcA[4];
    const __half* srcB[4];
#pragma unroll
    for (int i = 0; i < 4; i++) {
        int c   = tid + i * 256;
        int r   = c >> 3;
        int seg = c & 7;
        rA[i] = r; sA_[i] = seg;
        if (MODE == 1) {
            int m   = bm0 + r;
            int tok = ((m & (TN - 1)) == 0) ? 0 : ytok[m - 1];
            srcA[i] = Ab + (long)tok * lda + seg * 8;
        } else {
            srcA[i] = Ab + (long)(bm0 + r) * lda + seg * 8;
        }
        srcB[i] = Bb + (long)(bn0 + r) * ldb + seg * 8;
    }

    float acc[4][4][4];
#pragma unroll
    for (int i = 0; i < 4; i++)
#pragma unroll
        for (int j = 0; j < 4; j++)
#pragma unroll
            for (int q = 0; q < 4; q++) acc[i][j][q] = 0.f;

    const int nt = K / GBK;

    // prologue: issue up to 2 stages
#pragma unroll
    for (int s = 0; s < 2; s++) {
        if (s < nt) {
            __half* Ad = sh + s * STGH;
            __half* Bd = Ad + TSTG;
            int k0 = s * GBK;
#pragma unroll
            for (int i = 0; i < 4; i++) {
                cp16(&Ad[rA[i] * LDH + sA_[i] * 8], srcA[i] + k0);
                cp16(&Bd[rA[i] * LDH + sA_[i] * 8], srcB[i] + k0);
            }
            asm volatile("cp.async.commit_group;" ::: "memory");
        }
    }

    int buf = 0;
    for (int kt = 0; kt < nt; kt++) {
        if (kt + 1 < nt) {
            asm volatile("cp.async.wait_group 1;" ::: "memory");
        } else {
            asm volatile("cp.async.wait_group 0;" ::: "memory");
        }
        __syncthreads();

        if (kt + 2 < nt) {
            int sb2 = (kt + 2) % 3;
            __half* Ad = sh + sb2 * STGH;
            __half* Bd = Ad + TSTG;
            int k0 = (kt + 2) * GBK;
#pragma unroll
            for (int i = 0; i < 4; i++) {
                cp16(&Ad[rA[i] * LDH + sA_[i] * 8], srcA[i] + k0);
                cp16(&Bd[rA[i] * LDH + sA_[i] * 8], srcB[i] + k0);
            }
            asm volatile("cp.async.commit_group;" ::: "memory");
        }

        const __half* Asb = sh + buf * STGH;
        const __half* Bsb = Asb + TSTG;

#pragma unroll
        for (int kk = 0; kk < GBK; kk += 16) {
            unsigned af[4][4], bf[4][2];
#pragma unroll
            for (int mi = 0; mi < 4; mi++) {
                int row = wm * 64 + mi * 16 + lr + (quad & 1) * 8;
                int col = kk + (quad >> 1) * 8;
                unsigned addr = (unsigned)__cvta_generic_to_shared(
                    &Asb[row * LDH + col]);
                asm volatile(
                    "ldmatrix.sync.aligned.m8n8.x4.shared.b16 {%0,%1,%2,%3}, [%4];"
                    : "=r"(af[mi][0]), "=r"(af[mi][1]),
                      "=r"(af[mi][2]), "=r"(af[mi][3]) : "r"(addr));
            }
#pragma unroll
            for (int np = 0; np < 2; np++) {
                int row = wn * 32 + np * 16 + lr + (quad & 1) * 8;
                int col = kk + (quad >> 1) * 8;
                unsigned addr = (unsigned)__cvta_generic_to_shared(
                    &Bsb[row * LDH + col]);
                unsigned r0, r1, r2, r3;
                asm volatile(
                    "ldmatrix.sync.aligned.m8n8.x4.shared.b16 {%0,%1,%2,%3}, [%4];"
                    : "=r"(r0), "=r"(r1), "=r"(r2), "=r"(r3) : "r"(addr));
                bf[2 * np + 0][0] = r0; bf[2 * np + 0][1] = r2;
                bf[2 * np + 1][0] = r1; bf[2 * np + 1][1] = r3;
            }
#pragma unroll
            for (int mi = 0; mi < 4; mi++)
#pragma unroll
                for (int ni = 0; ni < 4; ni++)
                    asm volatile(
                        "mma.sync.aligned.m16n8k16.row.col.f32.f16.f16.f32 "
                        "{%0,%1,%2,%3}, {%4,%5,%6,%7}, {%8,%9}, {%0,%1,%2,%3};\n"
                        : "+f"(acc[mi][ni][0]), "+f"(acc[mi][ni][1]),
                          "+f"(acc[mi][ni][2]), "+f"(acc[mi][ni][3])
                        : "r"(af[mi][0]), "r"(af[mi][1]),
                          "r"(af[mi][2]), "r"(af[mi][3]),
                          "r"(bf[ni][0]), "r"(bf[ni][1]));
        }
        buf = (buf + 1) % 3;
        __syncthreads();
    }

    // ---------------- epilogue ----------------
#pragma unroll
    for (int mi = 0; mi < 4; mi++) {
#pragma unroll
        for (int ni = 0; ni < 4; ni++) {
            int row = bm0 + wm * 64 + mi * 16 + g;
            int col = bn0 + wn * 32 + ni * 8 + 2 * tq;
#pragma unroll
            for (int rr = 0; rr < 2; rr++) {
                int r = row + rr * 8;
                float v0 = acc[mi][ni][rr * 2 + 0];
                float v1 = acc[mi][ni][rr * 2 + 1];
                if (MODE == 2) {
                    int len = enc_len[z];
                    if (col     >= len) v0 = -1e9f;
                    if (col + 1 >= len) v1 = -1e9f;
                }
                if (MODE == 3) {
                    float bb = bias[r];
                    v0 += bb; v1 += bb;
                    int bidx = col >> 8;     // T = 256
                    int t    = col & 255;
                    *reinterpret_cast<float2*>(
                        (float*)Cv + (long)bidx * VOCABN * TN + (long)r * TN + t) =
                        make_float2(v0, v1);
                } else if (OUTH) {
                    __half2 h = __floats2half2_rn(v0, v1);
                    *reinterpret_cast<__half2*>(
                        (__half*)Cv + (long)z * sC + (long)r * ldc + col) = h;
                } else {
                    *reinterpret_cast<float2*>(
                        (float*)Cv + (long)z * sC + (long)r * ldc + col) =
                        make_float2(v0, v1);
                }
            }
        }
    }
}

// ---------------- elementwise LSTM-cell activation (zero state), fp16 out --------
__global__ void act_lstm(const float* __restrict__ gates,
                         const float* __restrict__ b_ih,
                         const float* __restrict__ b_hh,
                         __half* __restrict__ h,
                         __half* __restrict__ hcopy, int H, int ldcopy, long total)
{
    long idx = (long)blockIdx.x * blockDim.x + threadIdx.x;
    if (idx >= total) return;
    int  j = (int)(idx & (H - 1));
    long m = idx / H;
    const float* gr = gates + m * 4 * H;
    float iv = gr[j]         + b_ih[j]         + b_hh[j];
    float gv = gr[2 * H + j] + b_ih[2 * H + j] + b_hh[2 * H + j];
    float ov = gr[3 * H + j] + b_ih[3 * H + j] + b_hh[3 * H + j];
    float c  = sigf(iv) * tanhf(gv);
    __half hv = __float2half_rn(sigf(ov) * tanhf(c));
    h[m * H + j] = hv;
    if (hcopy) hcopy[m * ldcopy + j] = hv;
}

// ---------------- per-row softmax over S=512: fp32 in, fp16 out ----------------
__global__ void softmax_rows(const float* __restrict__ e, __half* __restrict__ a)
{
    const int row = blockIdx.x;
    const float* p = e + (long)row * SN;
    __half* q = a + (long)row * SN;
    __shared__ float red[128];
    int tid = threadIdx.x;
    float v0 = p[tid], v1 = p[tid + 128], v2 = p[tid + 256], v3 = p[tid + 384];
    float mx = fmaxf(fmaxf(v0, v1), fmaxf(v2, v3));
    red[tid] = mx; __syncthreads();
    for (int st = 64; st > 0; st >>= 1) {
        if (tid < st) red[tid] = fmaxf(red[tid], red[tid + st]);
        __syncthreads();
    }
    mx = red[0]; __syncthreads();
    v0 = expf(v0 - mx); v1 = expf(v1 - mx); v2 = expf(v2 - mx); v3 = expf(v3 - mx);
    float s = v0 + v1 + v2 + v3;
    red[tid] = s; __syncthreads();
    for (int st = 64; st > 0; st >>= 1) {
        if (tid < st) red[tid] += red[tid + st];
        __syncthreads();
    }
    float inv = 1.f / red[0];
    q[tid]       = __float2half_rn(v0 * inv);
    q[tid + 128] = __float2half_rn(v1 * inv);
    q[tid + 256] = __float2half_rn(v2 * inv);
    q[tid + 384] = __float2half_rn(v3 * inv);
}

// ---------------- value transpose: (B,S,KV) fp32 -> (B,KV,S) fp16 ----------------
__global__ void transpose_v(const float* __restrict__ v, __half* __restrict__ vt)
{
    __shared__ float tile[32][33];
    int b  = blockIdx.z;
    int s0 = blockIdx.y * 32, v0 = blockIdx.x * 32;
    int x = threadIdx.x, y = threadIdx.y;
#pragma unroll
    for (int i = 0; i < 32; i += 8)
        tile[y + i][x] = v[((long)b * SN + s0 + y + i) * KVN + v0 + x];
    __syncthreads();
#pragma unroll
    for (int i = 0; i < 32; i += 8)
        vt[((long)b * KVN + v0 + y + i) * SN + s0 + x] = __float2half_rn(tile[x][y + i]);
}

// ---------------- launch ----------------
extern "C" void kernel_launch(void* const* d_in, const int* in_sizes, int n_in,
                              void* d_out, int out_size)
{
    const float* key   = (const float*)d_in[0];
    const float* value = (const float*)d_in[1];
    const int*   elen  = (const int*)  d_in[2];
    const int*   y     = (const int*)  d_in[3];
    const float* E     = (const float*)d_in[4];
    const float* W1    = (const float*)d_in[5];
    const float* bi1   = (const float*)d_in[6];
    const float* bh1   = (const float*)d_in[7];
    const float* W2    = (const float*)d_in[8];
    const float* bi2   = (const float*)d_in[9];
    const float* bh2   = (const float*)d_in[10];
    const float* bout  = (const float*)d_in[11];
    float*       out   = (float*)d_out;

    float  *gates1, *gates2, *energy;
    __half *Eh, *W1h, *W2h, *keyh, *h1h, *h2h, *attnh, *valueTh, *outctxh;
    cudaGetSymbolAddress((void**)&gates1, g_gates1);
    cudaGetSymbolAddress((void**)&gates2, g_gates2);
    cudaGetSymbolAddress((void**)&energy, g_energy);
    cudaGetSymbolAddress((void**)&Eh,     g_Eh);
    cudaGetSymbolAddress((void**)&W1h,    g_W1h);
    cudaGetSymbolAddress((void**)&W2h,    g_W2h);
    cudaGetSymbolAddress((void**)&keyh,   g_keyh);
    cudaGetSymbolAddress((void**)&h1h,    g_h1h);
    cudaGetSymbolAddress((void**)&h2h,    g_h2h);
    cudaGetSymbolAddress((void**)&attnh,  g_attnh);
    cudaGetSymbolAddress((void**)&valueTh,g_valueTh);
    cudaGetSymbolAddress((void**)&outctxh,g_outctxh);

    cudaFuncSetAttribute(gemm_h<0,0>, cudaFuncAttributeMaxDynamicSharedMemorySize, GSMEM);
    cudaFuncSetAttribute(gemm_h<0,1>, cudaFuncAttributeMaxDynamicSharedMemorySize, GSMEM);
    cudaFuncSetAttribute(gemm_h<1,0>, cudaFuncAttributeMaxDynamicSharedMemorySize, GSMEM);
    cudaFuncSetAttribute(gemm_h<2,0>, cudaFuncAttributeMaxDynamicSharedMemorySize, GSMEM);
    cudaFuncSetAttribute(gemm_h<3,0>, cudaFuncAttributeMaxDynamicSharedMemorySize, GSMEM);

    // 0) convert static GEMM operands to fp16
    conv_h4<<<(VOCABN * EMBEDN / 4 + 255) / 256, 256>>>((const float4*)E,  (uint2*)Eh,  VOCABN * EMBEDN / 4);
    conv_h4<<<(4 * H1N * EMBEDN / 4 + 255) / 256, 256>>>((const float4*)W1, (uint2*)W1h, 4 * H1N * EMBEDN / 4);
    conv_h4<<<(4 * KVN * H1N / 4 + 255) / 256, 256>>>((const float4*)W2, (uint2*)W2h, 4 * KVN * H1N / 4);
    conv_h4<<<(BN_ * SN * KVN / 4 + 255) / 256, 256>>>((const float4*)key,(uint2*)keyh, BN_ * SN * KVN / 4);

    // 1) gates1 = embed(tokens) @ W1^T     (M=8192, N=2048, K=256) fp32 out
    gemm_h<1,0><<<dim3(2048 / GBN, MROWS / GBM, 1), 256, GSMEM>>>(
        Eh, W1h, gates1, EMBEDN, EMBEDN, EMBEDN, 4 * H1N,
        0, 0, 0, y, nullptr, nullptr);

    // 2) h1 = lstm_act(gates1) -> fp16
    {
        long total = (long)MROWS * H1N;
        act_lstm<<<(unsigned)((total + 255) / 256), 256>>>(
            gates1, bi1, bh1, h1h, nullptr, H1N, 0, total);
    }

    // 3) gates2 = h1 @ W2^T                (M=8192, N=512, K=512) fp32 out
    gemm_h<0,0><<<dim3(512 / GBN, MROWS / GBM, 1), 256, GSMEM>>>(
        h1h, W2h, gates2, H1N, H1N, H1N, 4 * KVN,
        0, 0, 0, nullptr, nullptr, nullptr);

    // 4) h2 = lstm_act(gates2) -> fp16; copy into out_ctx[:, 0:128]
    {
        long total = (long)MROWS * KVN;
        act_lstm<<<(unsigned)((total + 255) / 256), 256>>>(
            gates2, bi2, bh2, h2h, outctxh, KVN, EMBEDN, total);
    }

    // 5) valueT (fp16)
    transpose_v<<<dim3(KVN / 32, SN / 32, BN_), dim3(32, 8)>>>(value, valueTh);

    // 6) energy[b,t,s] = h2 . key, masked  (per b: M=256, N=512, K=128) fp32 out
    gemm_h<2,0><<<dim3(SN / GBN, TN / GBM, BN_), 256, GSMEM>>>(
        h2h, keyh, energy, KVN, KVN, KVN, SN,
        (long)TN * KVN, (long)SN * KVN, (long)TN * SN,
        nullptr, elen, nullptr);

    // 7) softmax -> fp16 attn
    softmax_rows<<<MROWS, 128>>>(energy, attnh);

    // 8) context = attn @ valueT -> out_ctx[:, 128:256] fp16
    gemm_h<0,1><<<dim3(KVN / GBN, TN / GBM, BN_), 256, GSMEM>>>(
        attnh, valueTh, outctxh + KVN, SN, SN, SN, EMBEDN,
        (long)TN * SN, (long)KVN * SN, (long)TN * EMBEDN,
        nullptr, nullptr, nullptr);

    // 9) logits = E @ out_ctx^T + b_out -> out[b][v][t]  (M=32000, N=8192, K=256)
    gemm_h<3,0><<<dim3(MROWS / GBN, VOCABN / GBM, 1), 256, GSMEM>>>(
        Eh, outctxh, out, EMBEDN, EMBEDN, EMBEDN, 0,
        0, 0, 0, nullptr, nullptr, bout);

    (void)in_sizes; (void)n_in; (void)out_size;
}

// round 8
// speedup vs baseline: 1.2602x; 1.0393x over previous
#include <cuda_runtime.h>
#include <cuda_fp16.h>
#include <cstdint>

#define VOCABN 32000
#define EMBEDN 256
#define H1N    512
#define KVN    128
#define BN_    32
#define SN     512
#define TN     256
#define MROWS  (BN_*TN)   // 8192

// ---------------- scratch (static device globals; no allocation) ----------------
__device__ float  g_gates1[MROWS * 4 * H1N];     // (only 3*H1N used now)
__device__ float  g_gates2[MROWS * 4 * KVN];     // (only 3*KVN used now)
__device__ float  g_energy[MROWS * SN];
__device__ __half g_Eh  [VOCABN * EMBEDN];
__device__ __half g_W1h [4 * H1N * EMBEDN];      // only 3*H1N rows used
__device__ __half g_W2h [4 * KVN * H1N];         // only 3*KVN rows used
__device__ __half g_keyh[BN_ * SN * KVN];
__device__ __half g_h1h [MROWS * H1N];
__device__ __half g_h2h [MROWS * KVN];
__device__ __half g_attnh[MROWS * SN];
__device__ __half g_valueTh[BN_ * KVN * SN];
__device__ __half g_outctxh[MROWS * EMBEDN];

// ---------------- helpers ----------------
__device__ __forceinline__ void cp16(void* dst_smem, const void* src) {
    unsigned s = (unsigned)__cvta_generic_to_shared(dst_smem);
    asm volatile("cp.async.cg.shared.global [%0], [%1], 16;" :: "r"(s), "l"(src));
}
__device__ __forceinline__ float sigf(float x) { return 1.f / (1.f + expf(-x)); }

// ---------------- fp32 -> fp16 convert ----------------
__global__ void conv_h4(const float4* __restrict__ src, uint2* __restrict__ dst, int n4)
{
    int i = blockIdx.x * blockDim.x + threadIdx.x;
    if (i < n4) {
        float4 v = src[i];
        __half2 h0 = __floats2half2_rn(v.x, v.y);
        __half2 h1 = __floats2half2_rn(v.z, v.w);
        uint2 o;
        o.x = *reinterpret_cast<unsigned*>(&h0);
        o.y = *reinterpret_cast<unsigned*>(&h1);
        dst[i] = o;
    }
}

// =================================================================================
// PERSISTENT-A logits GEMM: out[b][v][t] = sum_k E[v,k]*outctx[n,k] + bias[v]
// CTA: A-tile 128(vocab) x 256(k) resident in SMEM; loops over 8 N-tiles of 128,
// streaming B (outctx) chunks (128 x 64) through a 2-slot cp.async ring.
// 8 warps (2m x 4n), warp tile 64x32, 2 CTAs/SM.
// =================================================================================
#define PA_NT  8
#define LDHA   264                   // A smem row stride (halves): 256 + 8 pad
#define A_SMH  (128 * LDHA)          // 33792 halves = 67584 B
#define PB_LDH 72
#define B_SLOT (128 * PB_LDH)        // 9216 halves = 18432 B
#define PA_SMEM ((A_SMH + 2 * B_SLOT) * 2)   // 104448 B

__global__ void __launch_bounds__(256, 2)
logits_pa(const __half* __restrict__ Eh, const __half* __restrict__ Bm,
          const float* __restrict__ bias, float* __restrict__ out)
{
    extern __shared__ __half sh[];
    __half* Ash = sh;
    __half* Bsh = sh + A_SMH;

    const int tid  = threadIdx.x;
    const int warp = tid >> 5, lane = tid & 31;
    const int wm = warp >> 2, wn = warp & 3;
    const int g  = lane >> 2, tq = lane & 3;
    const int quad = lane >> 3, lr = lane & 7;
    const int bm0 = blockIdx.y * 128;       // vocab tile
    const int nt0 = blockIdx.x * PA_NT;     // first n-tile

    // ---- load resident A: 128 rows x 256 halves (16 chunks/thread) ----
#pragma unroll
    for (int i = 0; i < 16; i++) {
        int c = tid + i * 256;
        int r = c >> 5, seg = c & 31;
        cp16(&Ash[r * LDHA + seg * 8], Eh + (long)(bm0 + r) * EMBEDN + seg * 8);
    }
    asm volatile("cp.async.commit_group;" ::: "memory");

    // B chunk mapping: 1024 16B-chunks (4/thread)
    int rB[4], sB[4];
#pragma unroll
    for (int i = 0; i < 4; i++) {
        int c = tid + i * 256;
        rB[i] = c >> 3; sB[i] = c & 7;
    }

    // prologue: B chunks 0, 1
#pragma unroll
    for (int p = 0; p < 2; p++) {
        int nt = p >> 2, kc = p & 3;
        const __half* src = Bm + (long)((nt0 + nt) * 128) * EMBEDN + kc * 64;
#pragma unroll
        for (int i = 0; i < 4; i++)
            cp16(&Bsh[(p & 1) * B_SLOT + rB[i] * PB_LDH + sB[i] * 8],
                 src + (long)rB[i] * EMBEDN + sB[i] * 8);
        asm volatile("cp.async.commit_group;" ::: "memory");
    }

    // hoisted bias per thread (8 rows: mi x rr)
    float bb[8];
#pragma unroll
    for (int mi = 0; mi < 4; mi++)
#pragma unroll
        for (int rr = 0; rr < 2; rr++)
            bb[mi * 2 + rr] = bias[bm0 + wm * 64 + mi * 16 + g + rr * 8];

    float acc[4][4][4];
#pragma unroll
    for (int i = 0; i < 4; i++)
#pragma unroll
        for (int j = 0; j < 4; j++)
#pragma unroll
            for (int q = 0; q < 4; q++) acc[i][j][q] = 0.f;

    const int NCH = PA_NT * 4;
    for (int gch = 0; gch < NCH; gch++) {
        if (gch == NCH - 1) {
            asm volatile("cp.async.wait_group 0;" ::: "memory");
        } else {
            asm volatile("cp.async.wait_group 1;" ::: "memory");
        }
        __syncthreads();

        const __half* Bslot = Bsh + (gch & 1) * B_SLOT;
        const int kbase = (gch & 3) * 64;

#pragma unroll
        for (int kk = 0; kk < 64; kk += 16) {
            unsigned af[4][4], bf[4][2];
#pragma unroll
            for (int mi = 0; mi < 4; mi++) {
                int row = wm * 64 + mi * 16 + lr + (quad & 1) * 8;
                int col = kbase + kk + (quad >> 1) * 8;
                unsigned addr = (unsigned)__cvta_generic_to_shared(
                    &Ash[row * LDHA + col]);
                asm volatile(
                    "ldmatrix.sync.aligned.m8n8.x4.shared.b16 {%0,%1,%2,%3}, [%4];"
                    : "=r"(af[mi][0]), "=r"(af[mi][1]),
                      "=r"(af[mi][2]), "=r"(af[mi][3]) : "r"(addr));
            }
#pragma unroll
            for (int np = 0; np < 2; np++) {
                int row = wn * 32 + np * 16 + lr + (quad & 1) * 8;
                int col = kk + (quad >> 1) * 8;
                unsigned addr = (unsigned)__cvta_generic_to_shared(
                    &Bslot[row * PB_LDH + col]);
                unsigned r0, r1, r2, r3;
                asm volatile(
                    "ldmatrix.sync.aligned.m8n8.x4.shared.b16 {%0,%1,%2,%3}, [%4];"
                    : "=r"(r0), "=r"(r1), "=r"(r2), "=r"(r3) : "r"(addr));
                bf[2 * np + 0][0] = r0; bf[2 * np + 0][1] = r2;
                bf[2 * np + 1][0] = r1; bf[2 * np + 1][1] = r3;
            }
#pragma unroll
            for (int mi = 0; mi < 4; mi++)
#pragma unroll
                for (int ni = 0; ni < 4; ni++)
                    asm volatile(
                        "mma.sync.aligned.m16n8k16.row.col.f32.f16.f16.f32 "
                        "{%0,%1,%2,%3}, {%4,%5,%6,%7}, {%8,%9}, {%0,%1,%2,%3};\n"
                        : "+f"(acc[mi][ni][0]), "+f"(acc[mi][ni][1]),
                          "+f"(acc[mi][ni][2]), "+f"(acc[mi][ni][3])
                        : "r"(af[mi][0]), "r"(af[mi][1]),
                          "r"(af[mi][2]), "r"(af[mi][3]),
                          "r"(bf[ni][0]), "r"(bf[ni][1]));
        }
        __syncthreads();

        if (gch + 2 < NCH) {
            int g2 = gch + 2;
            int nt = g2 >> 2, kc = g2 & 3;
            const __half* src = Bm + (long)((nt0 + nt) * 128) * EMBEDN + kc * 64;
#pragma unroll
            for (int i = 0; i < 4; i++)
                cp16(&Bsh[(g2 & 1) * B_SLOT + rB[i] * PB_LDH + sB[i] * 8],
                     src + (long)rB[i] * EMBEDN + sB[i] * 8);
            asm volatile("cp.async.commit_group;" ::: "memory");
        }

        if ((gch & 3) == 3) {
            // epilogue for n-tile (nt0 + gch/4)
            int ncol0 = (nt0 + (gch >> 2)) * 128;
#pragma unroll
            for (int mi = 0; mi < 4; mi++) {
#pragma unroll
                for (int ni = 0; ni < 4; ni++) {
                    int row = bm0 + wm * 64 + mi * 16 + g;
                    int col = ncol0 + wn * 32 + ni * 8 + 2 * tq;
                    int bidx = col >> 8;
                    int t    = col & 255;
#pragma unroll
                    for (int rr = 0; rr < 2; rr++) {
                        int r = row + rr * 8;
                        float v0 = acc[mi][ni][rr * 2 + 0] + bb[mi * 2 + rr];
                        float v1 = acc[mi][ni][rr * 2 + 1] + bb[mi * 2 + rr];
                        *reinterpret_cast<float2*>(
                            out + (long)bidx * VOCABN * TN + (long)r * TN + t) =
                            make_float2(v0, v1);
                        acc[mi][ni][rr * 2 + 0] = 0.f;
                        acc[mi][ni][rr * 2 + 1] = 0.f;
                    }
                }
            }
        }
    }
}

// =================================================================================
// fp16 TN GEMM, CTA 128x128, BK=64, 3-stage cp.async (R7, verified)
// MODE 0: plain | MODE 1: token-gather A | MODE 2: energy mask | OUTH: fp16 out
// =================================================================================
#define GBM 128
#define GBN 128
#define GBK 64
#define LDH 72
#define TSTG (128 * LDH)
#define STGH (2 * TSTG)
#define GSMEM (3 * STGH * 2)

template <int MODE, int OUTH>
__global__ void __launch_bounds__(256, 2)
gemm_h(const __half* __restrict__ A, const __half* __restrict__ Bmat,
       void* __restrict__ Cv,
       int K, int lda, int ldb, int ldc,
       long sA, long sB, long sC,
       const int* __restrict__ ytok,
       const int* __restrict__ enc_len)
{
    extern __shared__ __half sh[];

    const int tid  = threadIdx.x;
    const int warp = tid >> 5, lane = tid & 31;
    const int wm = warp >> 2, wn = warp & 3;
    const int g  = lane >> 2, tq = lane & 3;
    const int quad = lane >> 3, lr = lane & 7;
    const int bm0 = blockIdx.y * GBM;
    const int bn0 = blockIdx.x * GBN;
    const int z   = blockIdx.z;

    const __half* Ab = A    + (long)z * sA;
    const __half* Bb = Bmat + (long)z * sB;

    int rA[4], sA_[4];
    const __half* srcA[4];
    const __half* srcB[4];
#pragma unroll
    for (int i = 0; i < 4; i++) {
        int c   = tid + i * 256;
        int r   = c >> 3;
        int seg = c & 7;
        rA[i] = r; sA_[i] = seg;
        if (MODE == 1) {
            int m   = bm0 + r;
            int tok = ((m & (TN - 1)) == 0) ? 0 : ytok[m - 1];
            srcA[i] = Ab + (long)tok * lda + seg * 8;
        } else {
            srcA[i] = Ab + (long)(bm0 + r) * lda + seg * 8;
        }
        srcB[i] = Bb + (long)(bn0 + r) * ldb + seg * 8;
    }

    float acc[4][4][4];
#pragma unroll
    for (int i = 0; i < 4; i++)
#pragma unroll
        for (int j = 0; j < 4; j++)
#pragma unroll
            for (int q = 0; q < 4; q++) acc[i][j][q] = 0.f;

    const int nt = K / GBK;

#pragma unroll
    for (int s = 0; s < 2; s++) {
        if (s < nt) {
            __half* Ad = sh + s * STGH;
            __half* Bd = Ad + TSTG;
            int k0 = s * GBK;
#pragma unroll
            for (int i = 0; i < 4; i++) {
                cp16(&Ad[rA[i] * LDH + sA_[i] * 8], srcA[i] + k0);
                cp16(&Bd[rA[i] * LDH + sA_[i] * 8], srcB[i] + k0);
            }
            asm volatile("cp.async.commit_group;" ::: "memory");
        }
    }

    int buf = 0;
    for (int kt = 0; kt < nt; kt++) {
        if (kt + 1 < nt) {
            asm volatile("cp.async.wait_group 1;" ::: "memory");
        } else {
            asm volatile("cp.async.wait_group 0;" ::: "memory");
        }
        __syncthreads();

        if (kt + 2 < nt) {
            int sb2 = (kt + 2) % 3;
            __half* Ad = sh + sb2 * STGH;
            __half* Bd = Ad + TSTG;
            int k0 = (kt + 2) * GBK;
#pragma unroll
            for (int i = 0; i < 4; i++) {
                cp16(&Ad[rA[i] * LDH + sA_[i] * 8], srcA[i] + k0);
                cp16(&Bd[rA[i] * LDH + sA_[i] * 8], srcB[i] + k0);
            }
            asm volatile("cp.async.commit_group;" ::: "memory");
        }

        const __half* Asb = sh + buf * STGH;
        const __half* Bsb = Asb + TSTG;

#pragma unroll
        for (int kk = 0; kk < GBK; kk += 16) {
            unsigned af[4][4], bf[4][2];
#pragma unroll
            for (int mi = 0; mi < 4; mi++) {
                int row = wm * 64 + mi * 16 + lr + (quad & 1) * 8;
                int col = kk + (quad >> 1) * 8;
                unsigned addr = (unsigned)__cvta_generic_to_shared(
                    &Asb[row * LDH + col]);
                asm volatile(
                    "ldmatrix.sync.aligned.m8n8.x4.shared.b16 {%0,%1,%2,%3}, [%4];"
                    : "=r"(af[mi][0]), "=r"(af[mi][1]),
                      "=r"(af[mi][2]), "=r"(af[mi][3]) : "r"(addr));
            }
#pragma unroll
            for (int np = 0; np < 2; np++) {
                int row = wn * 32 + np * 16 + lr + (quad & 1) * 8;
                int col = kk + (quad >> 1) * 8;
                unsigned addr = (unsigned)__cvta_generic_to_shared(
                    &Bsb[row * LDH + col]);
                unsigned r0, r1, r2, r3;
                asm volatile(
                    "ldmatrix.sync.aligned.m8n8.x4.shared.b16 {%0,%1,%2,%3}, [%4];"
                    : "=r"(r0), "=r"(r1), "=r"(r2), "=r"(r3) : "r"(addr));
                bf[2 * np + 0][0] = r0; bf[2 * np + 0][1] = r2;
                bf[2 * np + 1][0] = r1; bf[2 * np + 1][1] = r3;
            }
#pragma unroll
            for (int mi = 0; mi < 4; mi++)
#pragma unroll
                for (int ni = 0; ni < 4; ni++)
                    asm volatile(
                        "mma.sync.aligned.m16n8k16.row.col.f32.f16.f16.f32 "
                        "{%0,%1,%2,%3}, {%4,%5,%6,%7}, {%8,%9}, {%0,%1,%2,%3};\n"
                        : "+f"(acc[mi][ni][0]), "+f"(acc[mi][ni][1]),
                          "+f"(acc[mi][ni][2]), "+f"(acc[mi][ni][3])
                        : "r"(af[mi][0]), "r"(af[mi][1]),
                          "r"(af[mi][2]), "r"(af[mi][3]),
                          "r"(bf[ni][0]), "r"(bf[ni][1]));
        }
        buf = (buf + 1) % 3;
        __syncthreads();
    }

#pragma unroll
    for (int mi = 0; mi < 4; mi++) {
#pragma unroll
        for (int ni = 0; ni < 4; ni++) {
            int row = bm0 + wm * 64 + mi * 16 + g;
            int col = bn0 + wn * 32 + ni * 8 + 2 * tq;
#pragma unroll
            for (int rr = 0; rr < 2; rr++) {
                int r = row + rr * 8;
                float v0 = acc[mi][ni][rr * 2 + 0];
                float v1 = acc[mi][ni][rr * 2 + 1];
                if (MODE == 2) {
                    int len = enc_len[z];
                    if (col     >= len) v0 = -1e9f;
                    if (col + 1 >= len) v1 = -1e9f;
                }
                if (OUTH) {
                    __half2 h = __floats2half2_rn(v0, v1);
                    *reinterpret_cast<__half2*>(
                        (__half*)Cv + (long)z * sC + (long)r * ldc + col) = h;
                } else {
                    *reinterpret_cast<float2*>(
                        (float*)Cv + (long)z * sC + (long)r * ldc + col) =
                        make_float2(v0, v1);
                }
            }
        }
    }
}

// ---------------- LSTM activation: gates packed [i | g | o] (3H), fp16 out ------
__global__ void act_lstm(const float* __restrict__ gates,
                         const float* __restrict__ b_ih,
                         const float* __restrict__ b_hh,
                         __half* __restrict__ h,
                         __half* __restrict__ hcopy, int H, int ldcopy, long total)
{
    long idx = (long)blockIdx.x * blockDim.x + threadIdx.x;
    if (idx >= total) return;
    int  j = (int)(idx & (H - 1));
    long m = idx / H;
    const float* gr = gates + m * 3 * H;
    float iv = gr[j]         + b_ih[j]         + b_hh[j];
    float gv = gr[H + j]     + b_ih[2 * H + j] + b_hh[2 * H + j];
    float ov = gr[2 * H + j] + b_ih[3 * H + j] + b_hh[3 * H + j];
    float c  = sigf(iv) * tanhf(gv);
    __half hv = __float2half_rn(sigf(ov) * tanhf(c));
    h[m * H + j] = hv;
    if (hcopy) hcopy[m * ldcopy + j] = hv;
}

// ---------------- per-row softmax over S=512: fp32 in, fp16 out ----------------
__global__ void softmax_rows(const float* __restrict__ e, __half* __restrict__ a)
{
    const int row = blockIdx.x;
    const float* p = e + (long)row * SN;
    __half* q = a + (long)row * SN;
    __shared__ float red[128];
    int tid = threadIdx.x;
    float v0 = p[tid], v1 = p[tid + 128], v2 = p[tid + 256], v3 = p[tid + 384];
    float mx = fmaxf(fmaxf(v0, v1), fmaxf(v2, v3));
    red[tid] = mx; __syncthreads();
    for (int st = 64; st > 0; st >>= 1) {
        if (tid < st) red[tid] = fmaxf(red[tid], red[tid + st]);
        __syncthreads();
    }
    mx = red[0]; __syncthreads();
    v0 = expf(v0 - mx); v1 = expf(v1 - mx); v2 = expf(v2 - mx); v3 = expf(v3 - mx);
    float s = v0 + v1 + v2 + v3;
    red[tid] = s; __syncthreads();
    for (int st = 64; st > 0; st >>= 1) {
        if (tid < st) red[tid] += red[tid + st];
        __syncthreads();
    }
    float inv = 1.f / red[0];
    q[tid]       = __float2half_rn(v0 * inv);
    q[tid + 128] = __float2half_rn(v1 * inv);
    q[tid + 256] = __float2half_rn(v2 * inv);
    q[tid + 384] = __float2half_rn(v3 * inv);
}

// ---------------- value transpose: (B,S,KV) fp32 -> (B,KV,S) fp16 ----------------
__global__ void transpose_v(const float* __restrict__ v, __half* __restrict__ vt)
{
    __shared__ float tile[32][33];
    int b  = blockIdx.z;
    int s0 = blockIdx.y * 32, v0 = blockIdx.x * 32;
    int x = threadIdx.x, y = threadIdx.y;
#pragma unroll
    for (int i = 0; i < 32; i += 8)
        tile[y + i][x] = v[((long)b * SN + s0 + y + i) * KVN + v0 + x];
    __syncthreads();
#pragma unroll
    for (int i = 0; i < 32; i += 8)
        vt[((long)b * KVN + v0 + y + i) * SN + s0 + x] = __float2half_rn(tile[x][y + i]);
}

// ---------------- launch ----------------
extern "C" void kernel_launch(void* const* d_in, const int* in_sizes, int n_in,
                              void* d_out, int out_size)
{
    const float* key   = (const float*)d_in[0];
    const float* value = (const float*)d_in[1];
    const int*   elen  = (const int*)  d_in[2];
    const int*   y     = (const int*)  d_in[3];
    const float* E     = (const float*)d_in[4];
    const float* W1    = (const float*)d_in[5];
    const float* bi1   = (const float*)d_in[6];
    const float* bh1   = (const float*)d_in[7];
    const float* W2    = (const float*)d_in[8];
    const float* bi2   = (const float*)d_in[9];
    const float* bh2   = (const float*)d_in[10];
    const float* bout  = (const float*)d_in[11];
    float*       out   = (float*)d_out;

    float  *gates1, *gates2, *energy;
    __half *Eh, *W1h, *W2h, *keyh, *h1h, *h2h, *attnh, *valueTh, *outctxh;
    cudaGetSymbolAddress((void**)&gates1, g_gates1);
    cudaGetSymbolAddress((void**)&gates2, g_gates2);
    cudaGetSymbolAddress((void**)&energy, g_energy);
    cudaGetSymbolAddress((void**)&Eh,     g_Eh);
    cudaGetSymbolAddress((void**)&W1h,    g_W1h);
    cudaGetSymbolAddress((void**)&W2h,    g_W2h);
    cudaGetSymbolAddress((void**)&keyh,   g_keyh);
    cudaGetSymbolAddress((void**)&h1h,    g_h1h);
    cudaGetSymbolAddress((void**)&h2h,    g_h2h);
    cudaGetSymbolAddress((void**)&attnh,  g_attnh);
    cudaGetSymbolAddress((void**)&valueTh,g_valueTh);
    cudaGetSymbolAddress((void**)&outctxh,g_outctxh);

    cudaFuncSetAttribute(gemm_h<0,0>, cudaFuncAttributeMaxDynamicSharedMemorySize, GSMEM);
    cudaFuncSetAttribute(gemm_h<0,1>, cudaFuncAttributeMaxDynamicSharedMemorySize, GSMEM);
    cudaFuncSetAttribute(gemm_h<1,0>, cudaFuncAttributeMaxDynamicSharedMemorySize, GSMEM);
    cudaFuncSetAttribute(gemm_h<2,0>, cudaFuncAttributeMaxDynamicSharedMemorySize, GSMEM);
    cudaFuncSetAttribute(logits_pa, cudaFuncAttributeMaxDynamicSharedMemorySize, PA_SMEM);

    // 0) convert operands to fp16. W1/W2: keep only i,g,o gate rows (f is dead).
    conv_h4<<<(VOCABN * EMBEDN / 4 + 255) / 256, 256>>>((const float4*)E, (uint2*)Eh, VOCABN * EMBEDN / 4);
    {   // W1: i rows 0-511, g rows 1024-1535, o rows 1536-2047 -> packed 1536 rows
        int n4 = H1N * EMBEDN / 4;  // per gate chunk
        conv_h4<<<(n4 + 255) / 256, 256>>>((const float4*)W1,                      (uint2*)W1h,                     n4);
        conv_h4<<<(n4 + 255) / 256, 256>>>((const float4*)(W1 + 2 * H1N * EMBEDN), (uint2*)(W1h + H1N * EMBEDN),     n4);
        conv_h4<<<(n4 + 255) / 256, 256>>>((const float4*)(W1 + 3 * H1N * EMBEDN), (uint2*)(W1h + 2 * H1N * EMBEDN), n4);
    }
    {   // W2: i rows 0-127, g rows 256-383, o rows 384-511 -> packed 384 rows
        int n4 = KVN * H1N / 4;
        conv_h4<<<(n4 + 255) / 256, 256>>>((const float4*)W2,                    (uint2*)W2h,                   n4);
        conv_h4<<<(n4 + 255) / 256, 256>>>((const float4*)(W2 + 2 * KVN * H1N), (uint2*)(W2h + KVN * H1N),     n4);
        conv_h4<<<(n4 + 255) / 256, 256>>>((const float4*)(W2 + 3 * KVN * H1N), (uint2*)(W2h + 2 * KVN * H1N), n4);
    }
    conv_h4<<<(BN_ * SN * KVN / 4 + 255) / 256, 256>>>((const float4*)key, (uint2*)keyh, BN_ * SN * KVN / 4);

    // 1) gates1 = embed(tokens) @ W1'^T    (M=8192, N=1536, K=256)
    gemm_h<1,0><<<dim3(1536 / GBN, MROWS / GBM, 1), 256, GSMEM>>>(
        Eh, W1h, gates1, EMBEDN, EMBEDN, EMBEDN, 3 * H1N,
        0, 0, 0, y, nullptr);

    // 2) h1 = lstm_act(gates1) -> fp16
    {
        long total = (long)MROWS * H1N;
        act_lstm<<<(unsigned)((total + 255) / 256), 256>>>(
            gates1, bi1, bh1, h1h, nullptr, H1N, 0, total);
    }

    // 3) gates2 = h1 @ W2'^T               (M=8192, N=384, K=512)
    gemm_h<0,0><<<dim3(384 / GBN, MROWS / GBM, 1), 256, GSMEM>>>(
        h1h, W2h, gates2, H1N, H1N, H1N, 3 * KVN,
        0, 0, 0, nullptr, nullptr);

    // 4) h2 = lstm_act(gates2) -> fp16; copy into out_ctx[:, 0:128]
    {
        long total = (long)MROWS * KVN;
        act_lstm<<<(unsigned)((total + 255) / 256), 256>>>(
            gates2, bi2, bh2, h2h, outctxh, KVN, EMBEDN, total);
    }

    // 5) valueT (fp16)
    transpose_v<<<dim3(KVN / 32, SN / 32, BN_), dim3(32, 8)>>>(value, valueTh);

    // 6) energy[b,t,s] = h2 . key, masked  (per b: M=256, N=512, K=128)
    gemm_h<2,0><<<dim3(SN / GBN, TN / GBM, BN_), 256, GSMEM>>>(
        h2h, keyh, energy, KVN, KVN, KVN, SN,
        (long)TN * KVN, (long)SN * KVN, (long)TN * SN,
        nullptr, elen);

    // 7) softmax -> fp16 attn
    softmax_rows<<<MROWS, 128>>>(energy, attnh);

    // 8) context = attn @ valueT -> out_ctx[:, 128:256] fp16
    gemm_h<0,1><<<dim3(KVN / GBN, TN / GBM, BN_), 256, GSMEM>>>(
        attnh, valueTh, outctxh + KVN, SN, SN, SN, EMBEDN,
        (long)TN * SN, (long)KVN * SN, (long)TN * EMBEDN,
        nullptr, nullptr);

    // 9) logits = E @ out_ctx^T + b_out -> out[b][v][t]  (persistent-A)
    logits_pa<<<dim3((MROWS / 128) / PA_NT, VOCABN / 128), 256, PA_SMEM>>>(
        Eh, outctxh, bout, out);

    (void)in_sizes; (void)n_in; (void)out_size;
}

// round 9
// speedup vs baseline: 1.3158x; 1.0441x over previous
#include <cuda_runtime.h>
#include <cuda_fp16.h>
#include <cstdint>

#define VOCABN 32000
#define EMBEDN 256
#define H1N    512
#define KVN    128
#define BN_    32
#define SN     512
#define TN     256
#define MROWS  (BN_*TN)   // 8192

// ---------------- scratch (static device globals; no allocation) ----------------
__device__ float  g_gates1[MROWS * 3 * H1N];
__device__ float  g_gates2[MROWS * 3 * KVN];
__device__ __half g_Eh  [VOCABN * EMBEDN];
__device__ __half g_W1h [3 * H1N * EMBEDN];
__device__ __half g_W2h [3 * KVN * H1N];
__device__ __half g_keyh[BN_ * SN * KVN];
__device__ __half g_valueh[BN_ * SN * KVN];
__device__ __half g_h1h [MROWS * H1N];
__device__ __half g_outctxh[MROWS * EMBEDN];

// ---------------- helpers ----------------
__device__ __forceinline__ void cp16(void* dst_smem, const void* src) {
    unsigned s = (unsigned)__cvta_generic_to_shared(dst_smem);
    asm volatile("cp.async.cg.shared.global [%0], [%1], 16;" :: "r"(s), "l"(src));
}
__device__ __forceinline__ float sigf(float x) { return 1.f / (1.f + expf(-x)); }

// ---------------- one-shot fp32->fp16 conversion for ALL operands ----------------
// layout: [ E | W1 gates i,g,o | W2 gates i,g,o | key | value ]   (float4 units)
__global__ void conv_all(const float4* __restrict__ E,  const float4* __restrict__ W1,
                         const float4* __restrict__ W2, const float4* __restrict__ key,
                         const float4* __restrict__ value,
                         uint2* __restrict__ Eh,  uint2* __restrict__ W1h,
                         uint2* __restrict__ W2h, uint2* __restrict__ keyh,
                         uint2* __restrict__ valueh)
{
    const long nE   = (long)VOCABN * EMBEDN / 4;   // 2048000
    const long nW1g = H1N * EMBEDN / 4;            // 32768 (pow2)
    const long nW2g = KVN * H1N / 4;               // 16384 (pow2)
    const long nKey = (long)BN_ * SN * KVN / 4;    // 524288

    long o = (long)blockIdx.x * blockDim.x + threadIdx.x;
    const float4* src; uint2* dst; long si, di;
    if (o < nE) { src = E; dst = Eh; si = o; di = o; }
    else {
        o -= nE;
        if (o < 3 * nW1g) {
            long gate = o >> 15, r = o & (nW1g - 1);
            long sg = (gate == 0) ? 0 : gate + 1;        // i,g,o -> src 0,2,3
            src = W1; dst = W1h; si = sg * nW1g + r; di = o;
        } else {
            o -= 3 * nW1g;
            if (o < 3 * nW2g) {
                long gate = o >> 14, r = o & (nW2g - 1);
                long sg = (gate == 0) ? 0 : gate + 1;
                src = W2; dst = W2h; si = sg * nW2g + r; di = o;
            } else {
                o -= 3 * nW2g;
                if (o < nKey) { src = key; dst = keyh; si = o; di = o; }
                else {
                    o -= nKey;
                    if (o >= nKey) return;
                    src = value; dst = valueh; si = o; di = o;
                }
            }
        }
    }
    float4 v = src[si];
    __half2 h0 = __floats2half2_rn(v.x, v.y);
    __half2 h1 = __floats2half2_rn(v.z, v.w);
    uint2 out;
    out.x = *reinterpret_cast<unsigned*>(&h0);
    out.y = *reinterpret_cast<unsigned*>(&h1);
    dst[di] = out;
}
#define CONV_TOTAL (2048000 + 3*32768 + 3*16384 + 524288 + 524288)   // 3244032

// =================================================================================
// PERSISTENT-A logits GEMM (verified R8)
// =================================================================================
#define PA_NT  8
#define LDHA   264
#define A_SMH  (128 * LDHA)
#define PB_LDH 72
#define B_SLOT (128 * PB_LDH)
#define PA_SMEM ((A_SMH + 2 * B_SLOT) * 2)

__global__ void __launch_bounds__(256, 2)
logits_pa(const __half* __restrict__ Eh, const __half* __restrict__ Bm,
          const float* __restrict__ bias, float* __restrict__ out)
{
    extern __shared__ __half sh[];
    __half* Ash = sh;
    __half* Bsh = sh + A_SMH;

    const int tid  = threadIdx.x;
    const int warp = tid >> 5, lane = tid & 31;
    const int wm = warp >> 2, wn = warp & 3;
    const int g  = lane >> 2, tq = lane & 3;
    const int quad = lane >> 3, lr = lane & 7;
    const int bm0 = blockIdx.y * 128;
    const int nt0 = blockIdx.x * PA_NT;

#pragma unroll
    for (int i = 0; i < 16; i++) {
        int c = tid + i * 256;
        int r = c >> 5, seg = c & 31;
        cp16(&Ash[r * LDHA + seg * 8], Eh + (long)(bm0 + r) * EMBEDN + seg * 8);
    }
    asm volatile("cp.async.commit_group;" ::: "memory");

    int rB[4], sB[4];
#pragma unroll
    for (int i = 0; i < 4; i++) {
        int c = tid + i * 256;
        rB[i] = c >> 3; sB[i] = c & 7;
    }
#pragma unroll
    for (int p = 0; p < 2; p++) {
        int nt = p >> 2, kc = p & 3;
        const __half* src = Bm + (long)((nt0 + nt) * 128) * EMBEDN + kc * 64;
#pragma unroll
        for (int i = 0; i < 4; i++)
            cp16(&Bsh[(p & 1) * B_SLOT + rB[i] * PB_LDH + sB[i] * 8],
                 src + (long)rB[i] * EMBEDN + sB[i] * 8);
        asm volatile("cp.async.commit_group;" ::: "memory");
    }

    float bb[8];
#pragma unroll
    for (int mi = 0; mi < 4; mi++)
#pragma unroll
        for (int rr = 0; rr < 2; rr++)
            bb[mi * 2 + rr] = bias[bm0 + wm * 64 + mi * 16 + g + rr * 8];

    float acc[4][4][4];
#pragma unroll
    for (int i = 0; i < 4; i++)
#pragma unroll
        for (int j = 0; j < 4; j++)
#pragma unroll
            for (int q = 0; q < 4; q++) acc[i][j][q] = 0.f;

    const int NCH = PA_NT * 4;
    for (int gch = 0; gch < NCH; gch++) {
        if (gch == NCH - 1) {
            asm volatile("cp.async.wait_group 0;" ::: "memory");
        } else {
            asm volatile("cp.async.wait_group 1;" ::: "memory");
        }
        __syncthreads();

        const __half* Bslot = Bsh + (gch & 1) * B_SLOT;
        const int kbase = (gch & 3) * 64;

#pragma unroll
        for (int kk = 0; kk < 64; kk += 16) {
            unsigned af[4][4], bf[4][2];
#pragma unroll
            for (int mi = 0; mi < 4; mi++) {
                int row = wm * 64 + mi * 16 + lr + (quad & 1) * 8;
                int col = kbase + kk + (quad >> 1) * 8;
                unsigned addr = (unsigned)__cvta_generic_to_shared(
                    &Ash[row * LDHA + col]);
                asm volatile(
                    "ldmatrix.sync.aligned.m8n8.x4.shared.b16 {%0,%1,%2,%3}, [%4];"
                    : "=r"(af[mi][0]), "=r"(af[mi][1]),
                      "=r"(af[mi][2]), "=r"(af[mi][3]) : "r"(addr));
            }
#pragma unroll
            for (int np = 0; np < 2; np++) {
                int row = wn * 32 + np * 16 + lr + (quad & 1) * 8;
                int col = kk + (quad >> 1) * 8;
                unsigned addr = (unsigned)__cvta_generic_to_shared(
                    &Bslot[row * PB_LDH + col]);
                unsigned r0, r1, r2, r3;
                asm volatile(
                    "ldmatrix.sync.aligned.m8n8.x4.shared.b16 {%0,%1,%2,%3}, [%4];"
                    : "=r"(r0), "=r"(r1), "=r"(r2), "=r"(r3) : "r"(addr));
                bf[2 * np + 0][0] = r0; bf[2 * np + 0][1] = r2;
                bf[2 * np + 1][0] = r1; bf[2 * np + 1][1] = r3;
            }
#pragma unroll
            for (int mi = 0; mi < 4; mi++)
#pragma unroll
                for (int ni = 0; ni < 4; ni++)
                    asm volatile(
                        "mma.sync.aligned.m16n8k16.row.col.f32.f16.f16.f32 "
                        "{%0,%1,%2,%3}, {%4,%5,%6,%7}, {%8,%9}, {%0,%1,%2,%3};\n"
                        : "+f"(acc[mi][ni][0]), "+f"(acc[mi][ni][1]),
                          "+f"(acc[mi][ni][2]), "+f"(acc[mi][ni][3])
                        : "r"(af[mi][0]), "r"(af[mi][1]),
                          "r"(af[mi][2]), "r"(af[mi][3]),
                          "r"(bf[ni][0]), "r"(bf[ni][1]));
        }
        __syncthreads();

        if (gch + 2 < NCH) {
            int g2 = gch + 2;
            int nt = g2 >> 2, kc = g2 & 3;
            const __half* src = Bm + (long)((nt0 + nt) * 128) * EMBEDN + kc * 64;
#pragma unroll
            for (int i = 0; i < 4; i++)
                cp16(&Bsh[(g2 & 1) * B_SLOT + rB[i] * PB_LDH + sB[i] * 8],
                     src + (long)rB[i] * EMBEDN + sB[i] * 8);
            asm volatile("cp.async.commit_group;" ::: "memory");
        }

        if ((gch & 3) == 3) {
            int ncol0 = (nt0 + (gch >> 2)) * 128;
#pragma unroll
            for (int mi = 0; mi < 4; mi++) {
#pragma unroll
                for (int ni = 0; ni < 4; ni++) {
                    int row = bm0 + wm * 64 + mi * 16 + g;
                    int col = ncol0 + wn * 32 + ni * 8 + 2 * tq;
                    int bidx = col >> 8;
                    int t    = col & 255;
#pragma unroll
                    for (int rr = 0; rr < 2; rr++) {
                        int r = row + rr * 8;
                        float v0 = acc[mi][ni][rr * 2 + 0] + bb[mi * 2 + rr];
                        float v1 = acc[mi][ni][rr * 2 + 1] + bb[mi * 2 + rr];
                        *reinterpret_cast<float2*>(
                            out + (long)bidx * VOCABN * TN + (long)r * TN + t) =
                            make_float2(v0, v1);
                        acc[mi][ni][rr * 2 + 0] = 0.f;
                        acc[mi][ni][rr * 2 + 1] = 0.f;
                    }
                }
            }
        }
    }
}

// =================================================================================
// fp16 TN GEMM, CTA 128x128, BK=64, 3-stage cp.async (verified R7/R8)
// MODE 0: plain fp32 out | MODE 1: token-gather A, fp32 out
// =================================================================================
#define GBM 128
#define GBN 128
#define GBK 64
#define LDH 72
#define TSTG (128 * LDH)
#define STGH (2 * TSTG)
#define GSMEM (3 * STGH * 2)

template <int MODE>
__global__ void __launch_bounds__(256, 2)
gemm_h(const __half* __restrict__ A, const __half* __restrict__ Bmat,
       float* __restrict__ C,
       int K, int lda, int ldb, int ldc,
       const int* __restrict__ ytok)
{
    extern __shared__ __half sh[];

    const int tid  = threadIdx.x;
    const int warp = tid >> 5, lane = tid & 31;
    const int wm = warp >> 2, wn = warp & 3;
    const int g  = lane >> 2, tq = lane & 3;
    const int quad = lane >> 3, lr = lane & 7;
    const int bm0 = blockIdx.y * GBM;
    const int bn0 = blockIdx.x * GBN;

    int rA[4], sA_[4];
    const __half* srcA[4];
    const __half* srcB[4];
#pragma unroll
    for (int i = 0; i < 4; i++) {
        int c   = tid + i * 256;
        int r   = c >> 3;
        int seg = c & 7;
        rA[i] = r; sA_[i] = seg;
        if (MODE == 1) {
            int m   = bm0 + r;
            int tok = ((m & (TN - 1)) == 0) ? 0 : ytok[m - 1];
            srcA[i] = A + (long)tok * lda + seg * 8;
        } else {
            srcA[i] = A + (long)(bm0 + r) * lda + seg * 8;
        }
        srcB[i] = Bmat + (long)(bn0 + r) * ldb + seg * 8;
    }

    float acc[4][4][4];
#pragma unroll
    for (int i = 0; i < 4; i++)
#pragma unroll
        for (int j = 0; j < 4; j++)
#pragma unroll
            for (int q = 0; q < 4; q++) acc[i][j][q] = 0.f;

    const int nt = K / GBK;

#pragma unroll
    for (int s = 0; s < 2; s++) {
        if (s < nt) {
            __half* Ad = sh + s * STGH;
            __half* Bd = Ad + TSTG;
            int k0 = s * GBK;
#pragma unroll
            for (int i = 0; i < 4; i++) {
                cp16(&Ad[rA[i] * LDH + sA_[i] * 8], srcA[i] + k0);
                cp16(&Bd[rA[i] * LDH + sA_[i] * 8], srcB[i] + k0);
            }
            asm volatile("cp.async.commit_group;" ::: "memory");
        }
    }

    int buf = 0;
    for (int kt = 0; kt < nt; kt++) {
        if (kt + 1 < nt) {
            asm volatile("cp.async.wait_group 1;" ::: "memory");
        } else {
            asm volatile("cp.async.wait_group 0;" ::: "memory");
        }
        __syncthreads();

        if (kt + 2 < nt) {
            int sb2 = (kt + 2) % 3;
            __half* Ad = sh + sb2 * STGH;
            __half* Bd = Ad + TSTG;
            int k0 = (kt + 2) * GBK;
#pragma unroll
            for (int i = 0; i < 4; i++) {
                cp16(&Ad[rA[i] * LDH + sA_[i] * 8], srcA[i] + k0);
                cp16(&Bd[rA[i] * LDH + sA_[i] * 8], srcB[i] + k0);
            }
            asm volatile("cp.async.commit_group;" ::: "memory");
        }

        const __half* Asb = sh + buf * STGH;
        const __half* Bsb = Asb + TSTG;

#pragma unroll
        for (int kk = 0; kk < GBK; kk += 16) {
            unsigned af[4][4], bf[4][2];
#pragma unroll
            for (int mi = 0; mi < 4; mi++) {
                int row = wm * 64 + mi * 16 + lr + (quad & 1) * 8;
                int col = kk + (quad >> 1) * 8;
                unsigned addr = (unsigned)__cvta_generic_to_shared(
                    &Asb[row * LDH + col]);
                asm volatile(
                    "ldmatrix.sync.aligned.m8n8.x4.shared.b16 {%0,%1,%2,%3}, [%4];"
                    : "=r"(af[mi][0]), "=r"(af[mi][1]),
                      "=r"(af[mi][2]), "=r"(af[mi][3]) : "r"(addr));
            }
#pragma unroll
            for (int np = 0; np < 2; np++) {
                int row = wn * 32 + np * 16 + lr + (quad & 1) * 8;
                int col = kk + (quad >> 1) * 8;
                unsigned addr = (unsigned)__cvta_generic_to_shared(
                    &Bsb[row * LDH + col]);
                unsigned r0, r1, r2, r3;
                asm volatile(
                    "ldmatrix.sync.aligned.m8n8.x4.shared.b16 {%0,%1,%2,%3}, [%4];"
                    : "=r"(r0), "=r"(r1), "=r"(r2), "=r"(r3) : "r"(addr));
                bf[2 * np + 0][0] = r0; bf[2 * np + 0][1] = r2;
                bf[2 * np + 1][0] = r1; bf[2 * np + 1][1] = r3;
            }
#pragma unroll
            for (int mi = 0; mi < 4; mi++)
#pragma unroll
                for (int ni = 0; ni < 4; ni++)
                    asm volatile(
                        "mma.sync.aligned.m16n8k16.row.col.f32.f16.f16.f32 "
                        "{%0,%1,%2,%3}, {%4,%5,%6,%7}, {%8,%9}, {%0,%1,%2,%3};\n"
                        : "+f"(acc[mi][ni][0]), "+f"(acc[mi][ni][1]),
                          "+f"(acc[mi][ni][2]), "+f"(acc[mi][ni][3])
                        : "r"(af[mi][0]), "r"(af[mi][1]),
                          "r"(af[mi][2]), "r"(af[mi][3]),
                          "r"(bf[ni][0]), "r"(bf[ni][1]));
        }
        buf = (buf + 1) % 3;
        __syncthreads();
    }

#pragma unroll
    for (int mi = 0; mi < 4; mi++) {
#pragma unroll
        for (int ni = 0; ni < 4; ni++) {
            int row = bm0 + wm * 64 + mi * 16 + g;
            int col = bn0 + wn * 32 + ni * 8 + 2 * tq;
#pragma unroll
            for (int rr = 0; rr < 2; rr++) {
                int r = row + rr * 8;
                *reinterpret_cast<float2*>(C + (long)r * ldc + col) =
                    make_float2(acc[mi][ni][rr * 2 + 0], acc[mi][ni][rr * 2 + 1]);
            }
        }
    }
}

// ---------------- LSTM activation: gates packed [i | g | o] (3H), fp16 out ------
__global__ void act_lstm(const float* __restrict__ gates,
                         const float* __restrict__ b_ih,
                         const float* __restrict__ b_hh,
                         __half* __restrict__ h,
                         __half* __restrict__ hcopy, int H, int ldcopy, long total)
{
    long idx = (long)blockIdx.x * blockDim.x + threadIdx.x;
    if (idx >= total) return;
    int  j = (int)(idx & (H - 1));
    long m = idx / H;
    const float* gr = gates + m * 3 * H;
    float iv = gr[j]         + b_ih[j]         + b_hh[j];
    float gv = gr[H + j]     + b_ih[2 * H + j] + b_hh[2 * H + j];
    float ov = gr[2 * H + j] + b_ih[3 * H + j] + b_hh[3 * H + j];
    float c  = sigf(iv) * tanhf(gv);
    __half hv = __float2half_rn(sigf(ov) * tanhf(c));
    if (h)     h[m * H + j] = hv;
    if (hcopy) hcopy[m * ldcopy + j] = hv;
}

// =================================================================================
// Fused flash attention: energy + mask + softmax + context in one kernel.
// Grid (T/64, B). 4 warps x 16 t-rows. Q (64x128) resident; K/V streamed in
// 128-s chunks (double buffer). Online softmax fp32; P fp16 frags feed P@V mma.
// Writes context (fp16) into outctx[:, 128:256].
// =================================================================================
#define FA_LD  136
#define FA_QSZ (64 * FA_LD)
#define FA_KSZ (128 * FA_LD)
#define FA_SMEM ((FA_QSZ + 4 * FA_KSZ) * 2)   // 156672 bytes

#define LOAD_KV(sc_, bufi_) do { \
    const __half* ks_ = Km + ((long)b * SN + (sc_) * 128) * KVN; \
    const __half* vs_ = Vm + ((long)b * SN + (sc_) * 128) * KVN; \
    __half* kd_ = Ks + (bufi_) * FA_KSZ; \
    __half* vd_ = Vs + (bufi_) * FA_KSZ; \
    _Pragma("unroll") \
    for (int i_ = 0; i_ < 16; i_++) { \
        int c_ = tid + i_ * 128; \
        int r_ = c_ >> 4, sg_ = c_ & 15; \
        cp16(&kd_[r_ * FA_LD + sg_ * 8], ks_ + r_ * KVN + sg_ * 8); \
        cp16(&vd_[r_ * FA_LD + sg_ * 8], vs_ + r_ * KVN + sg_ * 8); \
    } \
    asm volatile("cp.async.commit_group;" ::: "memory"); \
} while (0)

__global__ void __launch_bounds__(128, 1)
fattn(const __half* __restrict__ Qm,   // outctxh (Q at cols 0..127), stride EMBEDN
      const __half* __restrict__ Km,   // keyh   [b][s][128]
      const __half* __restrict__ Vm,   // valueh [b][s][128]
      const int* __restrict__ enc_len,
      __half* __restrict__ Om)         // outctxh (store at cols 128..255)
{
    extern __shared__ __half sm[];
    __half* Qs = sm;
    __half* Ks = sm + FA_QSZ;
    __half* Vs = Ks + 2 * FA_KSZ;

    const int tid = threadIdx.x;
    const int warp = tid >> 5, lane = tid & 31;
    const int g = lane >> 2, tq = lane & 3;
    const int quad = lane >> 3, lr = lane & 7;
    const int b  = blockIdx.y;
    const int t0 = blockIdx.x * 64;
    const long qrow0 = (long)b * TN + t0;
    const int len = enc_len[b];

    // Q load: 64 rows x 16 segs = 1024 chunks / 128 threads = 8 each
#pragma unroll
    for (int i = 0; i < 8; i++) {
        int c = tid + i * 128;
        int r = c >> 4, seg = c & 15;
        cp16(&Qs[r * FA_LD + seg * 8], Qm + (qrow0 + r) * EMBEDN + seg * 8);
    }
    asm volatile("cp.async.commit_group;" ::: "memory");

    LOAD_KV(0, 0);
    LOAD_KV(1, 1);
    asm volatile("cp.async.wait_group 1;" ::: "memory");   // Q + kv0 done
    __syncthreads();

    // preload Q fragments (8 k-blocks of 16)
    unsigned qf[8][4];
#pragma unroll
    for (int kb = 0; kb < 8; kb++) {
        int row = warp * 16 + lr + (quad & 1) * 8;
        int col = kb * 16 + (quad >> 1) * 8;
        unsigned addr = (unsigned)__cvta_generic_to_shared(&Qs[row * FA_LD + col]);
        asm volatile(
            "ldmatrix.sync.aligned.m8n8.x4.shared.b16 {%0,%1,%2,%3}, [%4];"
            : "=r"(qf[kb][0]), "=r"(qf[kb][1]), "=r"(qf[kb][2]), "=r"(qf[kb][3])
            : "r"(addr));
    }

    float oacc[16][4];
#pragma unroll
    for (int i = 0; i < 16; i++)
#pragma unroll
        for (int q = 0; q < 4; q++) oacc[i][q] = 0.f;
    float m0 = -1e30f, m1 = -1e30f, l0 = 0.f, l1 = 0.f;

    for (int sc = 0; sc < 4; sc++) {
        if (sc == 1 || sc == 2) {
            asm volatile("cp.async.wait_group 1;" ::: "memory");
            __syncthreads();
        } else if (sc == 3) {
            asm volatile("cp.async.wait_group 0;" ::: "memory");
            __syncthreads();
        }
        const __half* Kb = Ks + (sc & 1) * FA_KSZ;
        const __half* Vb = Vs + (sc & 1) * FA_KSZ;

        // E = Q @ K^T   (16 rows x 128 s)
        float eacc[16][4];
#pragma unroll
        for (int i = 0; i < 16; i++)
#pragma unroll
            for (int q = 0; q < 4; q++) eacc[i][q] = 0.f;

#pragma unroll
        for (int kb = 0; kb < 8; kb++) {
#pragma unroll
            for (int np = 0; np < 8; np++) {
                int row = np * 16 + lr + (quad & 1) * 8;
                int col = kb * 16 + (quad >> 1) * 8;
                unsigned addr = (unsigned)__cvta_generic_to_shared(
                    &Kb[row * FA_LD + col]);
                unsigned r0, r1, r2, r3;
                asm volatile(
                    "ldmatrix.sync.aligned.m8n8.x4.shared.b16 {%0,%1,%2,%3}, [%4];"
                    : "=r"(r0), "=r"(r1), "=r"(r2), "=r"(r3) : "r"(addr));
                asm volatile(
                    "mma.sync.aligned.m16n8k16.row.col.f32.f16.f16.f32 "
                    "{%0,%1,%2,%3}, {%4,%5,%6,%7}, {%8,%9}, {%0,%1,%2,%3};\n"
                    : "+f"(eacc[2*np][0]), "+f"(eacc[2*np][1]),
                      "+f"(eacc[2*np][2]), "+f"(eacc[2*np][3])
                    : "r"(qf[kb][0]), "r"(qf[kb][1]), "r"(qf[kb][2]), "r"(qf[kb][3]),
                      "r"(r0), "r"(r2));
                asm volatile(
                    "mma.sync.aligned.m16n8k16.row.col.f32.f16.f16.f32 "
                    "{%0,%1,%2,%3}, {%4,%5,%6,%7}, {%8,%9}, {%0,%1,%2,%3};\n"
                    : "+f"(eacc[2*np+1][0]), "+f"(eacc[2*np+1][1]),
                      "+f"(eacc[2*np+1][2]), "+f"(eacc[2*np+1][3])
                    : "r"(qf[kb][0]), "r"(qf[kb][1]), "r"(qf[kb][2]), "r"(qf[kb][3]),
                      "r"(r1), "r"(r3));
            }
        }

        // mask + row max
        float mx0 = -1e30f, mx1 = -1e30f;
#pragma unroll
        for (int nb = 0; nb < 16; nb++) {
            int c0 = sc * 128 + nb * 8 + 2 * tq;
            if (c0 >= len)     { eacc[nb][0] = -1e9f; eacc[nb][2] = -1e9f; }
            if (c0 + 1 >= len) { eacc[nb][1] = -1e9f; eacc[nb][3] = -1e9f; }
            mx0 = fmaxf(mx0, fmaxf(eacc[nb][0], eacc[nb][1]));
            mx1 = fmaxf(mx1, fmaxf(eacc[nb][2], eacc[nb][3]));
        }
        mx0 = fmaxf(mx0, __shfl_xor_sync(0xffffffffu, mx0, 1));
        mx0 = fmaxf(mx0, __shfl_xor_sync(0xffffffffu, mx0, 2));
        mx1 = fmaxf(mx1, __shfl_xor_sync(0xffffffffu, mx1, 1));
        mx1 = fmaxf(mx1, __shfl_xor_sync(0xffffffffu, mx1, 2));

        float mn0 = fmaxf(m0, mx0), mn1 = fmaxf(m1, mx1);
        float cf0 = __expf(m0 - mn0), cf1 = __expf(m1 - mn1);
        m0 = mn0; m1 = mn1;
        l0 *= cf0; l1 *= cf1;
#pragma unroll
        for (int nb = 0; nb < 16; nb++) {
            oacc[nb][0] *= cf0; oacc[nb][1] *= cf0;
            oacc[nb][2] *= cf1; oacc[nb][3] *= cf1;
        }

        // P = exp(E - m), fp16 packed; row sums
        unsigned pf[16][2];
        float s0 = 0.f, s1 = 0.f;
#pragma unroll
        for (int nb = 0; nb < 16; nb++) {
            float p0 = __expf(eacc[nb][0] - m0);
            float p1 = __expf(eacc[nb][1] - m0);
            float p2 = __expf(eacc[nb][2] - m1);
            float p3 = __expf(eacc[nb][3] - m1);
            s0 += p0 + p1; s1 += p2 + p3;
            __half2 h01 = __floats2half2_rn(p0, p1);
            __half2 h23 = __floats2half2_rn(p2, p3);
            pf[nb][0] = *reinterpret_cast<unsigned*>(&h01);
            pf[nb][1] = *reinterpret_cast<unsigned*>(&h23);
        }
        s0 += __shfl_xor_sync(0xffffffffu, s0, 1);
        s0 += __shfl_xor_sync(0xffffffffu, s0, 2);
        s1 += __shfl_xor_sync(0xffffffffu, s1, 1);
        s1 += __shfl_xor_sync(0xffffffffu, s1, 2);
        l0 += s0; l1 += s1;

        // O += P @ V   (V B-frags via ldmatrix.trans on [s][v])
#pragma unroll
        for (int kb2 = 0; kb2 < 8; kb2++) {
            unsigned a0 = pf[2*kb2][0], a1 = pf[2*kb2][1];
            unsigned a2 = pf[2*kb2+1][0], a3 = pf[2*kb2+1][1];
#pragma unroll
            for (int vp = 0; vp < 8; vp++) {
                int row = kb2 * 16 + lr + (quad & 1) * 8;
                int col = vp * 16 + (quad >> 1) * 8;
                unsigned addr = (unsigned)__cvta_generic_to_shared(
                    &Vb[row * FA_LD + col]);
                unsigned r0, r1, r2, r3;
                asm volatile(
                    "ldmatrix.sync.aligned.m8n8.x4.trans.shared.b16 {%0,%1,%2,%3}, [%4];"
                    : "=r"(r0), "=r"(r1), "=r"(r2), "=r"(r3) : "r"(addr));
                asm volatile(
                    "mma.sync.aligned.m16n8k16.row.col.f32.f16.f16.f32 "
                    "{%0,%1,%2,%3}, {%4,%5,%6,%7}, {%8,%9}, {%0,%1,%2,%3};\n"
                    : "+f"(oacc[2*vp][0]), "+f"(oacc[2*vp][1]),
                      "+f"(oacc[2*vp][2]), "+f"(oacc[2*vp][3])
                    : "r"(a0), "r"(a1), "r"(a2), "r"(a3), "r"(r0), "r"(r1));
                asm volatile(
                    "mma.sync.aligned.m16n8k16.row.col.f32.f16.f16.f32 "
                    "{%0,%1,%2,%3}, {%4,%5,%6,%7}, {%8,%9}, {%0,%1,%2,%3};\n"
                    : "+f"(oacc[2*vp+1][0]), "+f"(oacc[2*vp+1][1]),
                      "+f"(oacc[2*vp+1][2]), "+f"(oacc[2*vp+1][3])
                    : "r"(a0), "r"(a1), "r"(a2), "r"(a3), "r"(r2), "r"(r3));
            }
        }

        __syncthreads();
        if (sc + 2 < 4) LOAD_KV(sc + 2, sc & 1);
    }

    // epilogue: O /= l, store fp16 into outctx[:, 128:256]
    float inv0 = 1.f / l0, inv1 = 1.f / l1;
    __half* orow0 = Om + (qrow0 + warp * 16 + g) * EMBEDN + KVN;
    __half* orow1 = orow0 + 8 * EMBEDN;
#pragma unroll
    for (int nb = 0; nb < 16; nb++) {
        int c = nb * 8 + 2 * tq;
        __half2 h0 = __floats2half2_rn(oacc[nb][0] * inv0, oacc[nb][1] * inv0);
        __half2 h1 = __floats2half2_rn(oacc[nb][2] * inv1, oacc[nb][3] * inv1);
        *reinterpret_cast<__half2*>(orow0 + c) = h0;
        *reinterpret_cast<__half2*>(orow1 + c) = h1;
    }
}

// ---------------- launch ----------------
extern "C" void kernel_launch(void* const* d_in, const int* in_sizes, int n_in,
                              void* d_out, int out_size)
{
    const float* key   = (const float*)d_in[0];
    const float* value = (const float*)d_in[1];
    const int*   elen  = (const int*)  d_in[2];
    const int*   y     = (const int*)  d_in[3];
    const float* E     = (const float*)d_in[4];
    const float* W1    = (const float*)d_in[5];
    const float* bi1   = (const float*)d_in[6];
    const float* bh1   = (const float*)d_in[7];
    const float* W2    = (const float*)d_in[8];
    const float* bi2   = (const float*)d_in[9];
    const float* bh2   = (const float*)d_in[10];
    const float* bout  = (const float*)d_in[11];
    float*       out   = (float*)d_out;

    float  *gates1, *gates2;
    __half *Eh, *W1h, *W2h, *keyh, *valueh, *h1h, *outctxh;
    cudaGetSymbolAddress((void**)&gates1, g_gates1);
    cudaGetSymbolAddress((void**)&gates2, g_gates2);
    cudaGetSymbolAddress((void**)&Eh,     g_Eh);
    cudaGetSymbolAddress((void**)&W1h,    g_W1h);
    cudaGetSymbolAddress((void**)&W2h,    g_W2h);
    cudaGetSymbolAddress((void**)&keyh,   g_keyh);
    cudaGetSymbolAddress((void**)&valueh, g_valueh);
    cudaGetSymbolAddress((void**)&h1h,    g_h1h);
    cudaGetSymbolAddress((void**)&outctxh,g_outctxh);

    cudaFuncSetAttribute(gemm_h<0>, cudaFuncAttributeMaxDynamicSharedMemorySize, GSMEM);
    cudaFuncSetAttribute(gemm_h<1>, cudaFuncAttributeMaxDynamicSharedMemorySize, GSMEM);
    cudaFuncSetAttribute(logits_pa, cudaFuncAttributeMaxDynamicSharedMemorySize, PA_SMEM);
    cudaFuncSetAttribute(fattn,     cudaFuncAttributeMaxDynamicSharedMemorySize, FA_SMEM);

    // 0) all fp16 conversions in one launch
    conv_all<<<CONV_TOTAL / 256, 256>>>(
        (const float4*)E, (const float4*)W1, (const float4*)W2,
        (const float4*)key, (const float4*)value,
        (uint2*)Eh, (uint2*)W1h, (uint2*)W2h, (uint2*)keyh, (uint2*)valueh);

    // 1) gates1 = embed(tokens) @ W1'^T    (M=8192, N=1536, K=256)
    gemm_h<1><<<dim3(1536 / GBN, MROWS / GBM), 256, GSMEM>>>(
        Eh, W1h, gates1, EMBEDN, EMBEDN, EMBEDN, 3 * H1N, y);

    // 2) h1 = lstm_act(gates1) -> fp16
    {
        long total = (long)MROWS * H1N;
        act_lstm<<<(unsigned)((total + 255) / 256), 256>>>(
            gates1, bi1, bh1, h1h, nullptr, H1N, 0, total);
    }

    // 3) gates2 = h1 @ W2'^T               (M=8192, N=384, K=512)
    gemm_h<0><<<dim3(384 / GBN, MROWS / GBM), 256, GSMEM>>>(
        h1h, W2h, gates2, H1N, H1N, H1N, 3 * KVN, nullptr);

    // 4) h2 = lstm_act(gates2) -> outctx[:, 0:128] only
    {
        long total = (long)MROWS * KVN;
        act_lstm<<<(unsigned)((total + 255) / 256), 256>>>(
            gates2, bi2, bh2, nullptr, outctxh, KVN, EMBEDN, total);
    }

    // 5) fused attention -> outctx[:, 128:256]
    fattn<<<dim3(TN / 64, BN_), 128, FA_SMEM>>>(
        outctxh, keyh, valueh, elen, outctxh);

    // 6) logits = E @ out_ctx^T + b_out -> out[b][v][t]
    logits_pa<<<dim3((MROWS / 128) / PA_NT, VOCABN / 128), 256, PA_SMEM>>>(
        Eh, outctxh, bout, out);

    (void)in_sizes; (void)n_in; (void)out_size;
}

// round 10
// speedup vs baseline: 1.3329x; 1.0130x over previous
#include <cuda_runtime.h>
#include <cuda_fp16.h>
#include <cstdint>

#define VOCABN 32000
#define EMBEDN 256
#define H1N    512
#define KVN    128
#define BN_    32
#define SN     512
#define TN     256
#define MROWS  (BN_*TN)   // 8192

// ---------------- scratch (static device globals; no allocation) ----------------
__device__ float  g_gates1[MROWS * 3 * H1N];
__device__ float  g_gates2[MROWS * 3 * KVN];
__device__ __half g_Eh  [VOCABN * EMBEDN];
__device__ __half g_W1h [3 * H1N * EMBEDN];
__device__ __half g_W2h [3 * KVN * H1N];
__device__ __half g_keyh[BN_ * SN * KVN];
__device__ __half g_valueh[BN_ * SN * KVN];
__device__ __half g_h1h [MROWS * H1N];
__device__ __half g_outctxh[MROWS * EMBEDN];

// ---------------- helpers ----------------
__device__ __forceinline__ void cp16(void* dst_smem, const void* src) {
    unsigned s = (unsigned)__cvta_generic_to_shared(dst_smem);
    asm volatile("cp.async.cg.shared.global [%0], [%1], 16;" :: "r"(s), "l"(src));
}
__device__ __forceinline__ float sigf(float x) { return 1.f / (1.f + expf(-x)); }

// ---------------- one-shot fp32->fp16 conversion for ALL operands ----------------
__global__ void conv_all(const float4* __restrict__ E,  const float4* __restrict__ W1,
                         const float4* __restrict__ W2, const float4* __restrict__ key,
                         const float4* __restrict__ value,
                         uint2* __restrict__ Eh,  uint2* __restrict__ W1h,
                         uint2* __restrict__ W2h, uint2* __restrict__ keyh,
                         uint2* __restrict__ valueh)
{
    const long nE   = (long)VOCABN * EMBEDN / 4;
    const long nW1g = H1N * EMBEDN / 4;
    const long nW2g = KVN * H1N / 4;
    const long nKey = (long)BN_ * SN * KVN / 4;

    long o = (long)blockIdx.x * blockDim.x + threadIdx.x;
    const float4* src; uint2* dst; long si, di;
    if (o < nE) { src = E; dst = Eh; si = o; di = o; }
    else {
        o -= nE;
        if (o < 3 * nW1g) {
            long gate = o >> 15, r = o & (nW1g - 1);
            long sg = (gate == 0) ? 0 : gate + 1;
            src = W1; dst = W1h; si = sg * nW1g + r; di = o;
        } else {
            o -= 3 * nW1g;
            if (o < 3 * nW2g) {
                long gate = o >> 14, r = o & (nW2g - 1);
                long sg = (gate == 0) ? 0 : gate + 1;
                src = W2; dst = W2h; si = sg * nW2g + r; di = o;
            } else {
                o -= 3 * nW2g;
                if (o < nKey) { src = key; dst = keyh; si = o; di = o; }
                else {
                    o -= nKey;
                    if (o >= nKey) return;
                    src = value; dst = valueh; si = o; di = o;
                }
            }
        }
    }
    float4 v = src[si];
    __half2 h0 = __floats2half2_rn(v.x, v.y);
    __half2 h1 = __floats2half2_rn(v.z, v.w);
    uint2 out;
    out.x = *reinterpret_cast<unsigned*>(&h0);
    out.y = *reinterpret_cast<unsigned*>(&h1);
    dst[di] = out;
}
#define CONV_TOTAL (2048000 + 3*32768 + 3*16384 + 524288 + 524288)

// =================================================================================
// PERSISTENT-A logits GEMM v2: 4 warps (2m x 2n), warp tile 64x64, 128 threads,
// 2 CTAs/SM. A 128x256 resident; B streamed in 128x64 chunks, 2-slot ring.
// =================================================================================
#define PA_NT  8
#define LDHA   264
#define A_SMH  (128 * LDHA)
#define PB_LDH 72
#define B_SLOT (128 * PB_LDH)
#define PA_SMEM ((A_SMH + 2 * B_SLOT) * 2)

__global__ void __launch_bounds__(128, 2)
logits_pa(const __half* __restrict__ Eh, const __half* __restrict__ Bm,
          const float* __restrict__ bias, float* __restrict__ out)
{
    extern __shared__ __half sh[];
    __half* Ash = sh;
    __half* Bsh = sh + A_SMH;

    const int tid  = threadIdx.x;
    const int warp = tid >> 5, lane = tid & 31;
    const int wm = warp >> 1, wn = warp & 1;
    const int g  = lane >> 2, tq = lane & 3;
    const int quad = lane >> 3, lr = lane & 7;
    const int bm0 = blockIdx.y * 128;
    const int nt0 = blockIdx.x * PA_NT;

    // resident A: 128 rows x 32 segs = 4096 chunks, 32 per thread
#pragma unroll
    for (int i = 0; i < 32; i++) {
        int c = tid + i * 128;
        int r = c >> 5, seg = c & 31;
        cp16(&Ash[r * LDHA + seg * 8], Eh + (long)(bm0 + r) * EMBEDN + seg * 8);
    }
    asm volatile("cp.async.commit_group;" ::: "memory");

    // B chunk mapping: 1024 chunks, 8 per thread
    int rB[8], sB[8];
#pragma unroll
    for (int i = 0; i < 8; i++) {
        int c = tid + i * 128;
        rB[i] = c >> 3; sB[i] = c & 7;
    }
#pragma unroll
    for (int p = 0; p < 2; p++) {
        int nt = p >> 2, kc = p & 3;
        const __half* src = Bm + (long)((nt0 + nt) * 128) * EMBEDN + kc * 64;
#pragma unroll
        for (int i = 0; i < 8; i++)
            cp16(&Bsh[(p & 1) * B_SLOT + rB[i] * PB_LDH + sB[i] * 8],
                 src + (long)rB[i] * EMBEDN + sB[i] * 8);
        asm volatile("cp.async.commit_group;" ::: "memory");
    }

    float bb[8];
#pragma unroll
    for (int mi = 0; mi < 4; mi++)
#pragma unroll
        for (int rr = 0; rr < 2; rr++)
            bb[mi * 2 + rr] = bias[bm0 + wm * 64 + mi * 16 + g + rr * 8];

    float acc[4][8][4];
#pragma unroll
    for (int i = 0; i < 4; i++)
#pragma unroll
        for (int j = 0; j < 8; j++)
#pragma unroll
            for (int q = 0; q < 4; q++) acc[i][j][q] = 0.f;

    const int NCH = PA_NT * 4;
    for (int gch = 0; gch < NCH; gch++) {
        if (gch == NCH - 1) {
            asm volatile("cp.async.wait_group 0;" ::: "memory");
        } else {
            asm volatile("cp.async.wait_group 1;" ::: "memory");
        }
        __syncthreads();

        const __half* Bslot = Bsh + (gch & 1) * B_SLOT;
        const int kbase = (gch & 3) * 64;

#pragma unroll
        for (int kk = 0; kk < 64; kk += 16) {
            unsigned af[4][4], bf[8][2];
#pragma unroll
            for (int mi = 0; mi < 4; mi++) {
                int row = wm * 64 + mi * 16 + lr + (quad & 1) * 8;
                int col = kbase + kk + (quad >> 1) * 8;
                unsigned addr = (unsigned)__cvta_generic_to_shared(
                    &Ash[row * LDHA + col]);
                asm volatile(
                    "ldmatrix.sync.aligned.m8n8.x4.shared.b16 {%0,%1,%2,%3}, [%4];"
                    : "=r"(af[mi][0]), "=r"(af[mi][1]),
                      "=r"(af[mi][2]), "=r"(af[mi][3]) : "r"(addr));
            }
#pragma unroll
            for (int np = 0; np < 4; np++) {
                int row = wn * 64 + np * 16 + lr + (quad & 1) * 8;
                int col = kk + (quad >> 1) * 8;
                unsigned addr = (unsigned)__cvta_generic_to_shared(
                    &Bslot[row * PB_LDH + col]);
                unsigned r0, r1, r2, r3;
                asm volatile(
                    "ldmatrix.sync.aligned.m8n8.x4.shared.b16 {%0,%1,%2,%3}, [%4];"
                    : "=r"(r0), "=r"(r1), "=r"(r2), "=r"(r3) : "r"(addr));
                bf[2 * np + 0][0] = r0; bf[2 * np + 0][1] = r2;
                bf[2 * np + 1][0] = r1; bf[2 * np + 1][1] = r3;
            }
#pragma unroll
            for (int mi = 0; mi < 4; mi++)
#pragma unroll
                for (int ni = 0; ni < 8; ni++)
                    asm volatile(
                        "mma.sync.aligned.m16n8k16.row.col.f32.f16.f16.f32 "
                        "{%0,%1,%2,%3}, {%4,%5,%6,%7}, {%8,%9}, {%0,%1,%2,%3};\n"
                        : "+f"(acc[mi][ni][0]), "+f"(acc[mi][ni][1]),
                          "+f"(acc[mi][ni][2]), "+f"(acc[mi][ni][3])
                        : "r"(af[mi][0]), "r"(af[mi][1]),
                          "r"(af[mi][2]), "r"(af[mi][3]),
                          "r"(bf[ni][0]), "r"(bf[ni][1]));
        }
        __syncthreads();

        if (gch + 2 < NCH) {
            int g2 = gch + 2;
            int nt = g2 >> 2, kc = g2 & 3;
            const __half* src = Bm + (long)((nt0 + nt) * 128) * EMBEDN + kc * 64;
#pragma unroll
            for (int i = 0; i < 8; i++)
                cp16(&Bsh[(g2 & 1) * B_SLOT + rB[i] * PB_LDH + sB[i] * 8],
                     src + (long)rB[i] * EMBEDN + sB[i] * 8);
            asm volatile("cp.async.commit_group;" ::: "memory");
        }

        if ((gch & 3) == 3) {
            int ncol0 = (nt0 + (gch >> 2)) * 128;
#pragma unroll
            for (int mi = 0; mi < 4; mi++) {
#pragma unroll
                for (int ni = 0; ni < 8; ni++) {
                    int row = bm0 + wm * 64 + mi * 16 + g;
                    int col = ncol0 + wn * 64 + ni * 8 + 2 * tq;
                    int bidx = col >> 8;
                    int t    = col & 255;
#pragma unroll
                    for (int rr = 0; rr < 2; rr++) {
                        int r = row + rr * 8;
                        float v0 = acc[mi][ni][rr * 2 + 0] + bb[mi * 2 + rr];
                        float v1 = acc[mi][ni][rr * 2 + 1] + bb[mi * 2 + rr];
                        *reinterpret_cast<float2*>(
                            out + (long)bidx * VOCABN * TN + (long)r * TN + t) =
                            make_float2(v0, v1);
                        acc[mi][ni][rr * 2 + 0] = 0.f;
                        acc[mi][ni][rr * 2 + 1] = 0.f;
                    }
                }
            }
        }
    }
}

// =================================================================================
// fp16 TN GEMM, CTA 128x128, BK=64, 3-stage cp.async (verified R7/R8)
// =================================================================================
#define GBM 128
#define GBN 128
#define GBK 64
#define LDH 72
#define TSTG (128 * LDH)
#define STGH (2 * TSTG)
#define GSMEM (3 * STGH * 2)

template <int MODE>
__global__ void __launch_bounds__(256, 2)
gemm_h(const __half* __restrict__ A, const __half* __restrict__ Bmat,
       float* __restrict__ C,
       int K, int lda, int ldb, int ldc,
       const int* __restrict__ ytok)
{
    extern __shared__ __half sh[];

    const int tid  = threadIdx.x;
    const int warp = tid >> 5, lane = tid & 31;
    const int wm = warp >> 2, wn = warp & 3;
    const int g  = lane >> 2, tq = lane & 3;
    const int quad = lane >> 3, lr = lane & 7;
    const int bm0 = blockIdx.y * GBM;
    const int bn0 = blockIdx.x * GBN;

    int rA[4], sA_[4];
    const __half* srcA[4];
    const __half* srcB[4];
#pragma unroll
    for (int i = 0; i < 4; i++) {
        int c   = tid + i * 256;
        int r   = c >> 3;
        int seg = c & 7;
        rA[i] = r; sA_[i] = seg;
        if (MODE == 1) {
            int m   = bm0 + r;
            int tok = ((m & (TN - 1)) == 0) ? 0 : ytok[m - 1];
            srcA[i] = A + (long)tok * lda + seg * 8;
        } else {
            srcA[i] = A + (long)(bm0 + r) * lda + seg * 8;
        }
        srcB[i] = Bmat + (long)(bn0 + r) * ldb + seg * 8;
    }

    float acc[4][4][4];
#pragma unroll
    for (int i = 0; i < 4; i++)
#pragma unroll
        for (int j = 0; j < 4; j++)
#pragma unroll
            for (int q = 0; q < 4; q++) acc[i][j][q] = 0.f;

    const int nt = K / GBK;

#pragma unroll
    for (int s = 0; s < 2; s++) {
        if (s < nt) {
            __half* Ad = sh + s * STGH;
            __half* Bd = Ad + TSTG;
            int k0 = s * GBK;
#pragma unroll
            for (int i = 0; i < 4; i++) {
                cp16(&Ad[rA[i] * LDH + sA_[i] * 8], srcA[i] + k0);
                cp16(&Bd[rA[i] * LDH + sA_[i] * 8], srcB[i] + k0);
            }
            asm volatile("cp.async.commit_group;" ::: "memory");
        }
    }

    int buf = 0;
    for (int kt = 0; kt < nt; kt++) {
        if (kt + 1 < nt) {
            asm volatile("cp.async.wait_group 1;" ::: "memory");
        } else {
            asm volatile("cp.async.wait_group 0;" ::: "memory");
        }
        __syncthreads();

        if (kt + 2 < nt) {
            int sb2 = (kt + 2) % 3;
            __half* Ad = sh + sb2 * STGH;
            __half* Bd = Ad + TSTG;
            int k0 = (kt + 2) * GBK;
#pragma unroll
            for (int i = 0; i < 4; i++) {
                cp16(&Ad[rA[i] * LDH + sA_[i] * 8], srcA[i] + k0);
                cp16(&Bd[rA[i] * LDH + sA_[i] * 8], srcB[i] + k0);
            }
            asm volatile("cp.async.commit_group;" ::: "memory");
        }

        const __half* Asb = sh + buf * STGH;
        const __half* Bsb = Asb + TSTG;

#pragma unroll
        for (int kk = 0; kk < GBK; kk += 16) {
            unsigned af[4][4], bf[4][2];
#pragma unroll
            for (int mi = 0; mi < 4; mi++) {
                int row = wm * 64 + mi * 16 + lr + (quad & 1) * 8;
                int col = kk + (quad >> 1) * 8;
                unsigned addr = (unsigned)__cvta_generic_to_shared(
                    &Asb[row * LDH + col]);
                asm volatile(
                    "ldmatrix.sync.aligned.m8n8.x4.shared.b16 {%0,%1,%2,%3}, [%4];"
                    : "=r"(af[mi][0]), "=r"(af[mi][1]),
                      "=r"(af[mi][2]), "=r"(af[mi][3]) : "r"(addr));
            }
#pragma unroll
            for (int np = 0; np < 2; np++) {
                int row = wn * 32 + np * 16 + lr + (quad & 1) * 8;
                int col = kk + (quad >> 1) * 8;
                unsigned addr = (unsigned)__cvta_generic_to_shared(
                    &Bsb[row * LDH + col]);
                unsigned r0, r1, r2, r3;
                asm volatile(
                    "ldmatrix.sync.aligned.m8n8.x4.shared.b16 {%0,%1,%2,%3}, [%4];"
                    : "=r"(r0), "=r"(r1), "=r"(r2), "=r"(r3) : "r"(addr));
                bf[2 * np + 0][0] = r0; bf[2 * np + 0][1] = r2;
                bf[2 * np + 1][0] = r1; bf[2 * np + 1][1] = r3;
            }
#pragma unroll
            for (int mi = 0; mi < 4; mi++)
#pragma unroll
                for (int ni = 0; ni < 4; ni++)
                    asm volatile(
                        "mma.sync.aligned.m16n8k16.row.col.f32.f16.f16.f32 "
                        "{%0,%1,%2,%3}, {%4,%5,%6,%7}, {%8,%9}, {%0,%1,%2,%3};\n"
                        : "+f"(acc[mi][ni][0]), "+f"(acc[mi][ni][1]),
                          "+f"(acc[mi][ni][2]), "+f"(acc[mi][ni][3])
                        : "r"(af[mi][0]), "r"(af[mi][1]),
                          "r"(af[mi][2]), "r"(af[mi][3]),
                          "r"(bf[ni][0]), "r"(bf[ni][1]));
        }
        buf = (buf + 1) % 3;
        __syncthreads();
    }

#pragma unroll
    for (int mi = 0; mi < 4; mi++) {
#pragma unroll
        for (int ni = 0; ni < 4; ni++) {
            int row = bm0 + wm * 64 + mi * 16 + g;
            int col = bn0 + wn * 32 + ni * 8 + 2 * tq;
#pragma unroll
            for (int rr = 0; rr < 2; rr++) {
                int r = row + rr * 8;
                *reinterpret_cast<float2*>(C + (long)r * ldc + col) =
                    make_float2(acc[mi][ni][rr * 2 + 0], acc[mi][ni][rr * 2 + 1]);
            }
        }
    }
}

// ---------------- LSTM activation: gates packed [i | g | o] (3H), fp16 out ------
__global__ void act_lstm(const float* __restrict__ gates,
                         const float* __restrict__ b_ih,
                         const float* __restrict__ b_hh,
                         __half* __restrict__ h,
                         __half* __restrict__ hcopy, int H, int ldcopy, long total)
{
    long idx = (long)blockIdx.x * blockDim.x + threadIdx.x;
    if (idx >= total) return;
    int  j = (int)(idx & (H - 1));
    long m = idx / H;
    const float* gr = gates + m * 3 * H;
    float iv = gr[j]         + b_ih[j]         + b_hh[j];
    float gv = gr[H + j]     + b_ih[2 * H + j] + b_hh[2 * H + j];
    float ov = gr[2 * H + j] + b_ih[3 * H + j] + b_hh[3 * H + j];
    float c  = sigf(iv) * tanhf(gv);
    __half hv = __float2half_rn(sigf(ov) * tanhf(c));
    if (h)     h[m * H + j] = hv;
    if (hcopy) hcopy[m * ldcopy + j] = hv;
}

// =================================================================================
// Fused flash attention (verified R9)
// =================================================================================
#define FA_LD  136
#define FA_QSZ (64 * FA_LD)
#define FA_KSZ (128 * FA_LD)
#define FA_SMEM ((FA_QSZ + 4 * FA_KSZ) * 2)

#define LOAD_KV(sc_, bufi_) do { \
    const __half* ks_ = Km + ((long)b * SN + (sc_) * 128) * KVN; \
    const __half* vs_ = Vm + ((long)b * SN + (sc_) * 128) * KVN; \
    __half* kd_ = Ks + (bufi_) * FA_KSZ; \
    __half* vd_ = Vs + (bufi_) * FA_KSZ; \
    _Pragma("unroll") \
    for (int i_ = 0; i_ < 16; i_++) { \
        int c_ = tid + i_ * 128; \
        int r_ = c_ >> 4, sg_ = c_ & 15; \
        cp16(&kd_[r_ * FA_LD + sg_ * 8], ks_ + r_ * KVN + sg_ * 8); \
        cp16(&vd_[r_ * FA_LD + sg_ * 8], vs_ + r_ * KVN + sg_ * 8); \
    } \
    asm volatile("cp.async.commit_group;" ::: "memory"); \
} while (0)

__global__ void __launch_bounds__(128, 1)
fattn(const __half* __restrict__ Qm,
      const __half* __restrict__ Km,
      const __half* __restrict__ Vm,
      const int* __restrict__ enc_len,
      __half* __restrict__ Om)
{
    extern __shared__ __half sm[];
    __half* Qs = sm;
    __half* Ks = sm + FA_QSZ;
    __half* Vs = Ks + 2 * FA_KSZ;

    const int tid = threadIdx.x;
    const int warp = tid >> 5, lane = tid & 31;
    const int g = lane >> 2, tq = lane & 3;
    const int quad = lane >> 3, lr = lane & 7;
    const int b  = blockIdx.y;
    const int t0 = blockIdx.x * 64;
    const long qrow0 = (long)b * TN + t0;
    const int len = enc_len[b];

#pragma unroll
    for (int i = 0; i < 8; i++) {
        int c = tid + i * 128;
        int r = c >> 4, seg = c & 15;
        cp16(&Qs[r * FA_LD + seg * 8], Qm + (qrow0 + r) * EMBEDN + seg * 8);
    }
    asm volatile("cp.async.commit_group;" ::: "memory");

    LOAD_KV(0, 0);
    LOAD_KV(1, 1);
    asm volatile("cp.async.wait_group 1;" ::: "memory");
    __syncthreads();

    unsigned qf[8][4];
#pragma unroll
    for (int kb = 0; kb < 8; kb++) {
        int row = warp * 16 + lr + (quad & 1) * 8;
        int col = kb * 16 + (quad >> 1) * 8;
        unsigned addr = (unsigned)__cvta_generic_to_shared(&Qs[row * FA_LD + col]);
        asm volatile(
            "ldmatrix.sync.aligned.m8n8.x4.shared.b16 {%0,%1,%2,%3}, [%4];"
            : "=r"(qf[kb][0]), "=r"(qf[kb][1]), "=r"(qf[kb][2]), "=r"(qf[kb][3])
            : "r"(addr));
    }

    float oacc[16][4];
#pragma unroll
    for (int i = 0; i < 16; i++)
#pragma unroll
        for (int q = 0; q < 4; q++) oacc[i][q] = 0.f;
    float m0 = -1e30f, m1 = -1e30f, l0 = 0.f, l1 = 0.f;

    for (int sc = 0; sc < 4; sc++) {
        if (sc == 1 || sc == 2) {
            asm volatile("cp.async.wait_group 1;" ::: "memory");
            __syncthreads();
        } else if (sc == 3) {
            asm volatile("cp.async.wait_group 0;" ::: "memory");
            __syncthreads();
        }
        const __half* Kb = Ks + (sc & 1) * FA_KSZ;
        const __half* Vb = Vs + (sc & 1) * FA_KSZ;

        float eacc[16][4];
#pragma unroll
        for (int i = 0; i < 16; i++)
#pragma unroll
            for (int q = 0; q < 4; q++) eacc[i][q] = 0.f;

#pragma unroll
        for (int kb = 0; kb < 8; kb++) {
#pragma unroll
            for (int np = 0; np < 8; np++) {
                int row = np * 16 + lr + (quad & 1) * 8;
                int col = kb * 16 + (quad >> 1) * 8;
                unsigned addr = (unsigned)__cvta_generic_to_shared(
                    &Kb[row * FA_LD + col]);
                unsigned r0, r1, r2, r3;
                asm volatile(
                    "ldmatrix.sync.aligned.m8n8.x4.shared.b16 {%0,%1,%2,%3}, [%4];"
                    : "=r"(r0), "=r"(r1), "=r"(r2), "=r"(r3) : "r"(addr));
                asm volatile(
                    "mma.sync.aligned.m16n8k16.row.col.f32.f16.f16.f32 "
                    "{%0,%1,%2,%3}, {%4,%5,%6,%7}, {%8,%9}, {%0,%1,%2,%3};\n"
                    : "+f"(eacc[2*np][0]), "+f"(eacc[2*np][1]),
                      "+f"(eacc[2*np][2]), "+f"(eacc[2*np][3])
                    : "r"(qf[kb][0]), "r"(qf[kb][1]), "r"(qf[kb][2]), "r"(qf[kb][3]),
                      "r"(r0), "r"(r2));
                asm volatile(
                    "mma.sync.aligned.m16n8k16.row.col.f32.f16.f16.f32 "
                    "{%0,%1,%2,%3}, {%4,%5,%6,%7}, {%8,%9}, {%0,%1,%2,%3};\n"
                    : "+f"(eacc[2*np+1][0]), "+f"(eacc[2*np+1][1]),
                      "+f"(eacc[2*np+1][2]), "+f"(eacc[2*np+1][3])
                    : "r"(qf[kb][0]), "r"(qf[kb][1]), "r"(qf[kb][2]), "r"(qf[kb][3]),
                      "r"(r1), "r"(r3));
            }
        }

        float mx0 = -1e30f, mx1 = -1e30f;
#pragma unroll
        for (int nb = 0; nb < 16; nb++) {
            int c0 = sc * 128 + nb * 8 + 2 * tq;
            if (c0 >= len)     { eacc[nb][0] = -1e9f; eacc[nb][2] = -1e9f; }
            if (c0 + 1 >= len) { eacc[nb][1] = -1e9f; eacc[nb][3] = -1e9f; }
            mx0 = fmaxf(mx0, fmaxf(eacc[nb][0], eacc[nb][1]));
            mx1 = fmaxf(mx1, fmaxf(eacc[nb][2], eacc[nb][3]));
        }
        mx0 = fmaxf(mx0, __shfl_xor_sync(0xffffffffu, mx0, 1));
        mx0 = fmaxf(mx0, __shfl_xor_sync(0xffffffffu, mx0, 2));
        mx1 = fmaxf(mx1, __shfl_xor_sync(0xffffffffu, mx1, 1));
        mx1 = fmaxf(mx1, __shfl_xor_sync(0xffffffffu, mx1, 2));

        float mn0 = fmaxf(m0, mx0), mn1 = fmaxf(m1, mx1);
        float cf0 = __expf(m0 - mn0), cf1 = __expf(m1 - mn1);
        m0 = mn0; m1 = mn1;
        l0 *= cf0; l1 *= cf1;
#pragma unroll
        for (int nb = 0; nb < 16; nb++) {
            oacc[nb][0] *= cf0; oacc[nb][1] *= cf0;
            oacc[nb][2] *= cf1; oacc[nb][3] *= cf1;
        }

        unsigned pf[16][2];
        float s0 = 0.f, s1 = 0.f;
#pragma unroll
        for (int nb = 0; nb < 16; nb++) {
            float p0 = __expf(eacc[nb][0] - m0);
            float p1 = __expf(eacc[nb][1] - m0);
            float p2 = __expf(eacc[nb][2] - m1);
            float p3 = __expf(eacc[nb][3] - m1);
            s0 += p0 + p1; s1 += p2 + p3;
            __half2 h01 = __floats2half2_rn(p0, p1);
            __half2 h23 = __floats2half2_rn(p2, p3);
            pf[nb][0] = *reinterpret_cast<unsigned*>(&h01);
            pf[nb][1] = *reinterpret_cast<unsigned*>(&h23);
        }
        s0 += __shfl_xor_sync(0xffffffffu, s0, 1);
        s0 += __shfl_xor_sync(0xffffffffu, s0, 2);
        s1 += __shfl_xor_sync(0xffffffffu, s1, 1);
        s1 += __shfl_xor_sync(0xffffffffu, s1, 2);
        l0 += s0; l1 += s1;

#pragma unroll
        for (int kb2 = 0; kb2 < 8; kb2++) {
            unsigned a0 = pf[2*kb2][0], a1 = pf[2*kb2][1];
            unsigned a2 = pf[2*kb2+1][0], a3 = pf[2*kb2+1][1];
#pragma unroll
            for (int vp = 0; vp < 8; vp++) {
                int row = kb2 * 16 + lr + (quad & 1) * 8;
                int col = vp * 16 + (quad >> 1) * 8;
                unsigned addr = (unsigned)__cvta_generic_to_shared(
                    &Vb[row * FA_LD + col]);
                unsigned r0, r1, r2, r3;
                asm volatile(
                    "ldmatrix.sync.aligned.m8n8.x4.trans.shared.b16 {%0,%1,%2,%3}, [%4];"
                    : "=r"(r0), "=r"(r1), "=r"(r2), "=r"(r3) : "r"(addr));
                asm volatile(
                    "mma.sync.aligned.m16n8k16.row.col.f32.f16.f16.f32 "
                    "{%0,%1,%2,%3}, {%4,%5,%6,%7}, {%8,%9}, {%0,%1,%2,%3};\n"
                    : "+f"(oacc[2*vp][0]), "+f"(oacc[2*vp][1]),
                      "+f"(oacc[2*vp][2]), "+f"(oacc[2*vp][3])
                    : "r"(a0), "r"(a1), "r"(a2), "r"(a3), "r"(r0), "r"(r1));
                asm volatile(
                    "mma.sync.aligned.m16n8k16.row.col.f32.f16.f16.f32 "
                    "{%0,%1,%2,%3}, {%4,%5,%6,%7}, {%8,%9}, {%0,%1,%2,%3};\n"
                    : "+f"(oacc[2*vp+1][0]), "+f"(oacc[2*vp+1][1]),
                      "+f"(oacc[2*vp+1][2]), "+f"(oacc[2*vp+1][3])
                    : "r"(a0), "r"(a1), "r"(a2), "r"(a3), "r"(r2), "r"(r3));
            }
        }

        __syncthreads();
        if (sc + 2 < 4) LOAD_KV(sc + 2, sc & 1);
    }

    float inv0 = 1.f / l0, inv1 = 1.f / l1;
    __half* orow0 = Om + (qrow0 + warp * 16 + g) * EMBEDN + KVN;
    __half* orow1 = orow0 + 8 * EMBEDN;
#pragma unroll
    for (int nb = 0; nb < 16; nb++) {
        int c = nb * 8 + 2 * tq;
        __half2 h0 = __floats2half2_rn(oacc[nb][0] * inv0, oacc[nb][1] * inv0);
        __half2 h1 = __floats2half2_rn(oacc[nb][2] * inv1, oacc[nb][3] * inv1);
        *reinterpret_cast<__half2*>(orow0 + c) = h0;
        *reinterpret_cast<__half2*>(orow1 + c) = h1;
    }
}

// ---------------- launch ----------------
extern "C" void kernel_launch(void* const* d_in, const int* in_sizes, int n_in,
                              void* d_out, int out_size)
{
    const float* key   = (const float*)d_in[0];
    const float* value = (const float*)d_in[1];
    const int*   elen  = (const int*)  d_in[2];
    const int*   y     = (const int*)  d_in[3];
    const float* E     = (const float*)d_in[4];
    const float* W1    = (const float*)d_in[5];
    const float* bi1   = (const float*)d_in[6];
    const float* bh1   = (const float*)d_in[7];
    const float* W2    = (const float*)d_in[8];
    const float* bi2   = (const float*)d_in[9];
    const float* bh2   = (const float*)d_in[10];
    const float* bout  = (const float*)d_in[11];
    float*       out   = (float*)d_out;

    float  *gates1, *gates2;
    __half *Eh, *W1h, *W2h, *keyh, *valueh, *h1h, *outctxh;
    cudaGetSymbolAddress((void**)&gates1, g_gates1);
    cudaGetSymbolAddress((void**)&gates2, g_gates2);
    cudaGetSymbolAddress((void**)&Eh,     g_Eh);
    cudaGetSymbolAddress((void**)&W1h,    g_W1h);
    cudaGetSymbolAddress((void**)&W2h,    g_W2h);
    cudaGetSymbolAddress((void**)&keyh,   g_keyh);
    cudaGetSymbolAddress((void**)&valueh, g_valueh);
    cudaGetSymbolAddress((void**)&h1h,    g_h1h);
    cudaGetSymbolAddress((void**)&outctxh,g_outctxh);

    cudaFuncSetAttribute(gemm_h<0>, cudaFuncAttributeMaxDynamicSharedMemorySize, GSMEM);
    cudaFuncSetAttribute(gemm_h<1>, cudaFuncAttributeMaxDynamicSharedMemorySize, GSMEM);
    cudaFuncSetAttribute(logits_pa, cudaFuncAttributeMaxDynamicSharedMemorySize, PA_SMEM);
    cudaFuncSetAttribute(fattn,     cudaFuncAttributeMaxDynamicSharedMemorySize, FA_SMEM);

    // 0) all fp16 conversions in one launch
    conv_all<<<CONV_TOTAL / 256, 256>>>(
        (const float4*)E, (const float4*)W1, (const float4*)W2,
        (const float4*)key, (const float4*)value,
        (uint2*)Eh, (uint2*)W1h, (uint2*)W2h, (uint2*)keyh, (uint2*)valueh);

    // 1) gates1 = embed(tokens) @ W1'^T    (M=8192, N=1536, K=256)
    gemm_h<1><<<dim3(1536 / GBN, MROWS / GBM), 256, GSMEM>>>(
        Eh, W1h, gates1, EMBEDN, EMBEDN, EMBEDN, 3 * H1N, y);

    // 2) h1 = lstm_act(gates1) -> fp16
    {
        long total = (long)MROWS * H1N;
        act_lstm<<<(unsigned)((total + 255) / 256), 256>>>(
            gates1, bi1, bh1, h1h, nullptr, H1N, 0, total);
    }

    // 3) gates2 = h1 @ W2'^T               (M=8192, N=384, K=512)
    gemm_h<0><<<dim3(384 / GBN, MROWS / GBM), 256, GSMEM>>>(
        h1h, W2h, gates2, H1N, H1N, H1N, 3 * KVN, nullptr);

    // 4) h2 = lstm_act(gates2) -> outctx[:, 0:128] only
    {
        long total = (long)MROWS * KVN;
        act_lstm<<<(unsigned)((total + 255) / 256), 256>>>(
            gates2, bi2, bh2, nullptr, outctxh, KVN, EMBEDN, total);
    }

    // 5) fused attention -> outctx[:, 128:256]
    fattn<<<dim3(TN / 64, BN_), 128, FA_SMEM>>>(
        outctxh, keyh, valueh, elen, outctxh);

    // 6) logits = E @ out_ctx^T + b_out -> out[b][v][t]
    logits_pa<<<dim3((MROWS / 128) / PA_NT, VOCABN / 128), 128, PA_SMEM>>>(
        Eh, outctxh, bout, out);

    (void)in_sizes; (void)n_in; (void)out_size;
}

// round 11
// speedup vs baseline: 1.4055x; 1.0545x over previous
#include <cuda_runtime.h>
#include <cuda_fp16.h>
#include <cstdint>

#define VOCABN 32000
#define EMBEDN 256
#define H1N    512
#define KVN    128
#define BN_    32
#define SN     512
#define TN     256
#define MROWS  (BN_*TN)   // 8192

// ---------------- scratch (static device globals; no allocation) ----------------
__device__ float  g_gates1[MROWS * 3 * H1N];
__device__ float  g_gates2[MROWS * 3 * KVN];
__device__ __half g_Eh  [VOCABN * EMBEDN];
__device__ __half g_W1h [3 * H1N * EMBEDN];
__device__ __half g_W2h [3 * KVN * H1N];
__device__ __half g_keyh[BN_ * SN * KVN];
__device__ __half g_valueh[BN_ * SN * KVN];
__device__ __half g_h1h [MROWS * H1N];
__device__ __half g_outctxh[MROWS * EMBEDN];

// ---------------- helpers ----------------
__device__ __forceinline__ void cp16(void* dst_smem, const void* src) {
    unsigned s = (unsigned)__cvta_generic_to_shared(dst_smem);
    asm volatile("cp.async.cg.shared.global [%0], [%1], 16;" :: "r"(s), "l"(src));
}
__device__ __forceinline__ float sigf(float x) { return 1.f / (1.f + expf(-x)); }

// ---------------- one-shot fp32->fp16 conversion for ALL operands ----------------
__global__ void conv_all(const float4* __restrict__ E,  const float4* __restrict__ W1,
                         const float4* __restrict__ W2, const float4* __restrict__ key,
                         const float4* __restrict__ value,
                         uint2* __restrict__ Eh,  uint2* __restrict__ W1h,
                         uint2* __restrict__ W2h, uint2* __restrict__ keyh,
                         uint2* __restrict__ valueh)
{
    const long nE   = (long)VOCABN * EMBEDN / 4;
    const long nW1g = H1N * EMBEDN / 4;
    const long nW2g = KVN * H1N / 4;
    const long nKey = (long)BN_ * SN * KVN / 4;

    long o = (long)blockIdx.x * blockDim.x + threadIdx.x;
    const float4* src; uint2* dst; long si, di;
    if (o < nE) { src = E; dst = Eh; si = o; di = o; }
    else {
        o -= nE;
        if (o < 3 * nW1g) {
            long gate = o >> 15, r = o & (nW1g - 1);
            long sg = (gate == 0) ? 0 : gate + 1;
            src = W1; dst = W1h; si = sg * nW1g + r; di = o;
        } else {
            o -= 3 * nW1g;
            if (o < 3 * nW2g) {
                long gate = o >> 14, r = o & (nW2g - 1);
                long sg = (gate == 0) ? 0 : gate + 1;
                src = W2; dst = W2h; si = sg * nW2g + r; di = o;
            } else {
                o -= 3 * nW2g;
                if (o < nKey) { src = key; dst = keyh; si = o; di = o; }
                else {
                    o -= nKey;
                    if (o >= nKey) return;
                    src = value; dst = valueh; si = o; di = o;
                }
            }
        }
    }
    float4 v = src[si];
    __half2 h0 = __floats2half2_rn(v.x, v.y);
    __half2 h1 = __floats2half2_rn(v.z, v.w);
    uint2 out;
    out.x = *reinterpret_cast<unsigned*>(&h0);
    out.y = *reinterpret_cast<unsigned*>(&h1);
    dst[di] = out;
}
#define CONV_TOTAL (2048000 + 3*32768 + 3*16384 + 524288 + 524288)

// =================================================================================
// PERSISTENT-A logits GEMM v3: 4 warps (2m x 2n), warp tile 64x64, 128 threads,
// 2 CTAs/SM. A 128x256 resident (XOR-swizzled, no pad); B streamed in 128x64
// chunks through a 3-slot XOR-swizzled ring -> ONE sync per chunk, 2-deep
// prefetch. Output stores use streaming (.cs) hint.
// =================================================================================
#define PA_NT  8
#define A_STR  256                    // halves per A row (no pad, swizzled)
#define A_SMH  (128 * A_STR)          // 32768 halves = 65536 B
#define B_STR  64                     // halves per B row (no pad, swizzled)
#define B_SLOT (128 * B_STR)          // 8192 halves = 16384 B
#define PA_SMEM ((A_SMH + 3 * B_SLOT) * 2)   // 114688 B

__global__ void __launch_bounds__(128, 2)
logits_pa(const __half* __restrict__ Eh, const __half* __restrict__ Bm,
          const float* __restrict__ bias, float* __restrict__ out)
{
    extern __shared__ __half sh[];
    __half* Ash = sh;
    __half* Bsh = sh + A_SMH;

    const int tid  = threadIdx.x;
    const int warp = tid >> 5, lane = tid & 31;
    const int wm = warp >> 1, wn = warp & 1;
    const int g  = lane >> 2, tq = lane & 3;
    const int quad = lane >> 3, lr = lane & 7;
    const int bm0 = blockIdx.y * 128;
    const int nt0 = blockIdx.x * PA_NT;

    // ---- resident A: 128 rows x 32 segs, swizzled seg^(r&7) ----
#pragma unroll
    for (int i = 0; i < 32; i++) {
        int c = tid + i * 128;
        int r = c >> 5, seg = c & 31;
        int sw = (seg & 7) ^ (r & 7);
        int segw = (seg & ~7) | sw;
        cp16(&Ash[r * A_STR + segw * 8], Eh + (long)(bm0 + r) * EMBEDN + seg * 8);
    }
    asm volatile("cp.async.commit_group;" ::: "memory");

    // B chunk mapping: 1024 chunks, 8 per thread
    int rB[8], sB[8], swB[8];
#pragma unroll
    for (int i = 0; i < 8; i++) {
        int c = tid + i * 128;
        rB[i] = c >> 3; sB[i] = c & 7;
        swB[i] = sB[i] ^ (rB[i] & 7);
    }
    // prologue: B chunks 0, 1 into slots 0, 1
#pragma unroll
    for (int p = 0; p < 2; p++) {
        const __half* src = Bm + (long)(nt0 * 128) * EMBEDN + p * 64;
#pragma unroll
        for (int i = 0; i < 8; i++)
            cp16(&Bsh[p * B_SLOT + rB[i] * B_STR + swB[i] * 8],
                 src + (long)rB[i] * EMBEDN + sB[i] * 8);
        asm volatile("cp.async.commit_group;" ::: "memory");
    }

    float bb[8];
#pragma unroll
    for (int mi = 0; mi < 4; mi++)
#pragma unroll
        for (int rr = 0; rr < 2; rr++)
            bb[mi * 2 + rr] = bias[bm0 + wm * 64 + mi * 16 + g + rr * 8];

    float acc[4][8][4];
#pragma unroll
    for (int i = 0; i < 4; i++)
#pragma unroll
        for (int j = 0; j < 8; j++)
#pragma unroll
            for (int q = 0; q < 4; q++) acc[i][j][q] = 0.f;

    const int NCH = PA_NT * 4;
    int slot = 0;
    for (int gch = 0; gch < NCH; gch++) {
        if (gch == NCH - 1) {
            asm volatile("cp.async.wait_group 0;" ::: "memory");
        } else {
            asm volatile("cp.async.wait_group 1;" ::: "memory");
        }
        __syncthreads();   // single sync per chunk

        // prefetch chunk gch+2 into slot (gch+2)%3 (== slot of gch-1, now free)
        if (gch + 2 < NCH) {
            int g2 = gch + 2;
            int nt = g2 >> 2, kc = g2 & 3;
            int s2 = g2 % 3;
            const __half* src = Bm + (long)((nt0 + nt) * 128) * EMBEDN + kc * 64;
#pragma unroll
            for (int i = 0; i < 8; i++)
                cp16(&Bsh[s2 * B_SLOT + rB[i] * B_STR + swB[i] * 8],
                     src + (long)rB[i] * EMBEDN + sB[i] * 8);
            asm volatile("cp.async.commit_group;" ::: "memory");
        }

        const __half* Bslot = Bsh + slot * B_SLOT;
        const int kbase = (gch & 3) * 64;

#pragma unroll
        for (int kk = 0; kk < 64; kk += 16) {
            unsigned af[4][4], bf[8][2];
#pragma unroll
            for (int mi = 0; mi < 4; mi++) {
                int row = wm * 64 + mi * 16 + lr + (quad & 1) * 8;
                int seg = ((kbase + kk) >> 3) + (quad >> 1);
                int segw = (seg & ~7) | ((seg & 7) ^ (row & 7));
                unsigned addr = (unsigned)__cvta_generic_to_shared(
                    &Ash[row * A_STR + segw * 8]);
                asm volatile(
                    "ldmatrix.sync.aligned.m8n8.x4.shared.b16 {%0,%1,%2,%3}, [%4];"
                    : "=r"(af[mi][0]), "=r"(af[mi][1]),
                      "=r"(af[mi][2]), "=r"(af[mi][3]) : "r"(addr));
            }
#pragma unroll
            for (int np = 0; np < 4; np++) {
                int row = wn * 64 + np * 16 + lr + (quad & 1) * 8;
                int seg = (kk >> 3) + (quad >> 1);
                int segw = seg ^ (row & 7);
                unsigned addr = (unsigned)__cvta_generic_to_shared(
                    &Bslot[row * B_STR + segw * 8]);
                unsigned r0, r1, r2, r3;
                asm volatile(
                    "ldmatrix.sync.aligned.m8n8.x4.shared.b16 {%0,%1,%2,%3}, [%4];"
                    : "=r"(r0), "=r"(r1), "=r"(r2), "=r"(r3) : "r"(addr));
                bf[2 * np + 0][0] = r0; bf[2 * np + 0][1] = r2;
                bf[2 * np + 1][0] = r1; bf[2 * np + 1][1] = r3;
            }
#pragma unroll
            for (int mi = 0; mi < 4; mi++)
#pragma unroll
                for (int ni = 0; ni < 8; ni++)
                    asm volatile(
                        "mma.sync.aligned.m16n8k16.row.col.f32.f16.f16.f32 "
                        "{%0,%1,%2,%3}, {%4,%5,%6,%7}, {%8,%9}, {%0,%1,%2,%3};\n"
                        : "+f"(acc[mi][ni][0]), "+f"(acc[mi][ni][1]),
                          "+f"(acc[mi][ni][2]), "+f"(acc[mi][ni][3])
                        : "r"(af[mi][0]), "r"(af[mi][1]),
                          "r"(af[mi][2]), "r"(af[mi][3]),
                          "r"(bf[ni][0]), "r"(bf[ni][1]));
        }
        slot = (slot + 1 == 3) ? 0 : slot + 1;

        if ((gch & 3) == 3) {
            int ncol0 = (nt0 + (gch >> 2)) * 128;
#pragma unroll
            for (int mi = 0; mi < 4; mi++) {
#pragma unroll
                for (int ni = 0; ni < 8; ni++) {
                    int row = bm0 + wm * 64 + mi * 16 + g;
                    int col = ncol0 + wn * 64 + ni * 8 + 2 * tq;
                    int bidx = col >> 8;
                    int t    = col & 255;
#pragma unroll
                    for (int rr = 0; rr < 2; rr++) {
                        int r = row + rr * 8;
                        float v0 = acc[mi][ni][rr * 2 + 0] + bb[mi * 2 + rr];
                        float v1 = acc[mi][ni][rr * 2 + 1] + bb[mi * 2 + rr];
                        __stcs(reinterpret_cast<float2*>(
                                   out + (long)bidx * VOCABN * TN + (long)r * TN + t),
                               make_float2(v0, v1));
                        acc[mi][ni][rr * 2 + 0] = 0.f;
                        acc[mi][ni][rr * 2 + 1] = 0.f;
                    }
                }
            }
        }
    }
}

// =================================================================================
// fp16 TN GEMM, CTA 128x128, BK=64, 3-stage cp.async (verified R7/R8)
// =================================================================================
#define GBM 128
#define GBN 128
#define GBK 64
#define LDH 72
#define TSTG (128 * LDH)
#define STGH (2 * TSTG)
#define GSMEM (3 * STGH * 2)

template <int MODE>
__global__ void __launch_bounds__(256, 2)
gemm_h(const __half* __restrict__ A, const __half* __restrict__ Bmat,
       float* __restrict__ C,
       int K, int lda, int ldb, int ldc,
       const int* __restrict__ ytok)
{
    extern __shared__ __half sh[];

    const int tid  = threadIdx.x;
    const int warp = tid >> 5, lane = tid & 31;
    const int wm = warp >> 2, wn = warp & 3;
    const int g  = lane >> 2, tq = lane & 3;
    const int quad = lane >> 3, lr = lane & 7;
    const int bm0 = blockIdx.y * GBM;
    const int bn0 = blockIdx.x * GBN;

    int rA[4], sA_[4];
    const __half* srcA[4];
    const __half* srcB[4];
#pragma unroll
    for (int i = 0; i < 4; i++) {
        int c   = tid + i * 256;
        int r   = c >> 3;
        int seg = c & 7;
        rA[i] = r; sA_[i] = seg;
        if (MODE == 1) {
            int m   = bm0 + r;
            int tok = ((m & (TN - 1)) == 0) ? 0 : ytok[m - 1];
            srcA[i] = A + (long)tok * lda + seg * 8;
        } else {
            srcA[i] = A + (long)(bm0 + r) * lda + seg * 8;
        }
        srcB[i] = Bmat + (long)(bn0 + r) * ldb + seg * 8;
    }

    float acc[4][4][4];
#pragma unroll
    for (int i = 0; i < 4; i++)
#pragma unroll
        for (int j = 0; j < 4; j++)
#pragma unroll
            for (int q = 0; q < 4; q++) acc[i][j][q] = 0.f;

    const int nt = K / GBK;

#pragma unroll
    for (int s = 0; s < 2; s++) {
        if (s < nt) {
            __half* Ad = sh + s * STGH;
            __half* Bd = Ad + TSTG;
            int k0 = s * GBK;
#pragma unroll
            for (int i = 0; i < 4; i++) {
                cp16(&Ad[rA[i] * LDH + sA_[i] * 8], srcA[i] + k0);
                cp16(&Bd[rA[i] * LDH + sA_[i] * 8], srcB[i] + k0);
            }
            asm volatile("cp.async.commit_group;" ::: "memory");
        }
    }

    int buf = 0;
    for (int kt = 0; kt < nt; kt++) {
        if (kt + 1 < nt) {
            asm volatile("cp.async.wait_group 1;" ::: "memory");
        } else {
            asm volatile("cp.async.wait_group 0;" ::: "memory");
        }
        __syncthreads();

        if (kt + 2 < nt) {
            int sb2 = (kt + 2) % 3;
            __half* Ad = sh + sb2 * STGH;
            __half* Bd = Ad + TSTG;
            int k0 = (kt + 2) * GBK;
#pragma unroll
            for (int i = 0; i < 4; i++) {
                cp16(&Ad[rA[i] * LDH + sA_[i] * 8], srcA[i] + k0);
                cp16(&Bd[rA[i] * LDH + sA_[i] * 8], srcB[i] + k0);
            }
            asm volatile("cp.async.commit_group;" ::: "memory");
        }

        const __half* Asb = sh + buf * STGH;
        const __half* Bsb = Asb + TSTG;

#pragma unroll
        for (int kk = 0; kk < GBK; kk += 16) {
            unsigned af[4][4], bf[4][2];
#pragma unroll
            for (int mi = 0; mi < 4; mi++) {
                int row = wm * 64 + mi * 16 + lr + (quad & 1) * 8;
                int col = kk + (quad >> 1) * 8;
                unsigned addr = (unsigned)__cvta_generic_to_shared(
                    &Asb[row * LDH + col]);
                asm volatile(
                    "ldmatrix.sync.aligned.m8n8.x4.shared.b16 {%0,%1,%2,%3}, [%4];"
                    : "=r"(af[mi][0]), "=r"(af[mi][1]),
                      "=r"(af[mi][2]), "=r"(af[mi][3]) : "r"(addr));
            }
#pragma unroll
            for (int np = 0; np < 2; np++) {
                int row = wn * 32 + np * 16 + lr + (quad & 1) * 8;
                int col = kk + (quad >> 1) * 8;
                unsigned addr = (unsigned)__cvta_generic_to_shared(
                    &Bsb[row * LDH + col]);
                unsigned r0, r1, r2, r3;
                asm volatile(
                    "ldmatrix.sync.aligned.m8n8.x4.shared.b16 {%0,%1,%2,%3}, [%4];"
                    : "=r"(r0), "=r"(r1), "=r"(r2), "=r"(r3) : "r"(addr));
                bf[2 * np + 0][0] = r0; bf[2 * np + 0][1] = r2;
                bf[2 * np + 1][0] = r1; bf[2 * np + 1][1] = r3;
            }
#pragma unroll
            for (int mi = 0; mi < 4; mi++)
#pragma unroll
                for (int ni = 0; ni < 4; ni++)
                    asm volatile(
                        "mma.sync.aligned.m16n8k16.row.col.f32.f16.f16.f32 "
                        "{%0,%1,%2,%3}, {%4,%5,%6,%7}, {%8,%9}, {%0,%1,%2,%3};\n"
                        : "+f"(acc[mi][ni][0]), "+f"(acc[mi][ni][1]),
                          "+f"(acc[mi][ni][2]), "+f"(acc[mi][ni][3])
                        : "r"(af[mi][0]), "r"(af[mi][1]),
                          "r"(af[mi][2]), "r"(af[mi][3]),
                          "r"(bf[ni][0]), "r"(bf[ni][1]));
        }
        buf = (buf + 1) % 3;
        __syncthreads();
    }

#pragma unroll
    for (int mi = 0; mi < 4; mi++) {
#pragma unroll
        for (int ni = 0; ni < 4; ni++) {
            int row = bm0 + wm * 64 + mi * 16 + g;
            int col = bn0 + wn * 32 + ni * 8 + 2 * tq;
#pragma unroll
            for (int rr = 0; rr < 2; rr++) {
                int r = row + rr * 8;
                *reinterpret_cast<float2*>(C + (long)r * ldc + col) =
                    make_float2(acc[mi][ni][rr * 2 + 0], acc[mi][ni][rr * 2 + 1]);
            }
        }
    }
}

// ---------------- LSTM activation: gates packed [i | g | o] (3H), fp16 out ------
__global__ void act_lstm(const float* __restrict__ gates,
                         const float* __restrict__ b_ih,
                         const float* __restrict__ b_hh,
                         __half* __restrict__ h,
                         __half* __restrict__ hcopy, int H, int ldcopy, long total)
{
    long idx = (long)blockIdx.x * blockDim.x + threadIdx.x;
    if (idx >= total) return;
    int  j = (int)(idx & (H - 1));
    long m = idx / H;
    const float* gr = gates + m * 3 * H;
    float iv = gr[j]         + b_ih[j]         + b_hh[j];
    float gv = gr[H + j]     + b_ih[2 * H + j] + b_hh[2 * H + j];
    float ov = gr[2 * H + j] + b_ih[3 * H + j] + b_hh[3 * H + j];
    float c  = sigf(iv) * tanhf(gv);
    __half hv = __float2half_rn(sigf(ov) * tanhf(c));
    if (h)     h[m * H + j] = hv;
    if (hcopy) hcopy[m * ldcopy + j] = hv;
}

// =================================================================================
// Fused flash attention (verified R9)
// =================================================================================
#define FA_LD  136
#define FA_QSZ (64 * FA_LD)
#define FA_KSZ (128 * FA_LD)
#define FA_SMEM ((FA_QSZ + 4 * FA_KSZ) * 2)

#define LOAD_KV(sc_, bufi_) do { \
    const __half* ks_ = Km + ((long)b * SN + (sc_) * 128) * KVN; \
    const __half* vs_ = Vm + ((long)b * SN + (sc_) * 128) * KVN; \
    __half* kd_ = Ks + (bufi_) * FA_KSZ; \
    __half* vd_ = Vs + (bufi_) * FA_KSZ; \
    _Pragma("unroll") \
    for (int i_ = 0; i_ < 16; i_++) { \
        int c_ = tid + i_ * 128; \
        int r_ = c_ >> 4, sg_ = c_ & 15; \
        cp16(&kd_[r_ * FA_LD + sg_ * 8], ks_ + r_ * KVN + sg_ * 8); \
        cp16(&vd_[r_ * FA_LD + sg_ * 8], vs_ + r_ * KVN + sg_ * 8); \
    } \
    asm volatile("cp.async.commit_group;" ::: "memory"); \
} while (0)

__global__ void __launch_bounds__(128, 1)
fattn(const __half* __restrict__ Qm,
      const __half* __restrict__ Km,
      const __half* __restrict__ Vm,
      const int* __restrict__ enc_len,
      __half* __restrict__ Om)
{
    extern __shared__ __half sm[];
    __half* Qs = sm;
    __half* Ks = sm + FA_QSZ;
    __half* Vs = Ks + 2 * FA_KSZ;

    const int tid = threadIdx.x;
    const int warp = tid >> 5, lane = tid & 31;
    const int g = lane >> 2, tq = lane & 3;
    const int quad = lane >> 3, lr = lane & 7;
    const int b  = blockIdx.y;
    const int t0 = blockIdx.x * 64;
    const long qrow0 = (long)b * TN + t0;
    const int len = enc_len[b];

#pragma unroll
    for (int i = 0; i < 8; i++) {
        int c = tid + i * 128;
        int r = c >> 4, seg = c & 15;
        cp16(&Qs[r * FA_LD + seg * 8], Qm + (qrow0 + r) * EMBEDN + seg * 8);
    }
    asm volatile("cp.async.commit_group;" ::: "memory");

    LOAD_KV(0, 0);
    LOAD_KV(1, 1);
    asm volatile("cp.async.wait_group 1;" ::: "memory");
    __syncthreads();

    unsigned qf[8][4];
#pragma unroll
    for (int kb = 0; kb < 8; kb++) {
        int row = warp * 16 + lr + (quad & 1) * 8;
        int col = kb * 16 + (quad >> 1) * 8;
        unsigned addr = (unsigned)__cvta_generic_to_shared(&Qs[row * FA_LD + col]);
        asm volatile(
            "ldmatrix.sync.aligned.m8n8.x4.shared.b16 {%0,%1,%2,%3}, [%4];"
            : "=r"(qf[kb][0]), "=r"(qf[kb][1]), "=r"(qf[kb][2]), "=r"(qf[kb][3])
            : "r"(addr));
    }

    float oacc[16][4];
#pragma unroll
    for (int i = 0; i < 16; i++)
#pragma unroll
        for (int q = 0; q < 4; q++) oacc[i][q] = 0.f;
    float m0 = -1e30f, m1 = -1e30f, l0 = 0.f, l1 = 0.f;

    for (int sc = 0; sc < 4; sc++) {
        if (sc == 1 || sc == 2) {
            asm volatile("cp.async.wait_group 1;" ::: "memory");
            __syncthreads();
        } else if (sc == 3) {
            asm volatile("cp.async.wait_group 0;" ::: "memory");
            __syncthreads();
        }
        const __half* Kb = Ks + (sc & 1) * FA_KSZ;
        const __half* Vb = Vs + (sc & 1) * FA_KSZ;

        float eacc[16][4];
#pragma unroll
        for (int i = 0; i < 16; i++)
#pragma unroll
            for (int q = 0; q < 4; q++) eacc[i][q] = 0.f;

#pragma unroll
        for (int kb = 0; kb < 8; kb++) {
#pragma unroll
            for (int np = 0; np < 8; np++) {
                int row = np * 16 + lr + (quad & 1) * 8;
                int col = kb * 16 + (quad >> 1) * 8;
                unsigned addr = (unsigned)__cvta_generic_to_shared(
                    &Kb[row * FA_LD + col]);
                unsigned r0, r1, r2, r3;
                asm volatile(
                    "ldmatrix.sync.aligned.m8n8.x4.shared.b16 {%0,%1,%2,%3}, [%4];"
                    : "=r"(r0), "=r"(r1), "=r"(r2), "=r"(r3) : "r"(addr));
                asm volatile(
                    "mma.sync.aligned.m16n8k16.row.col.f32.f16.f16.f32 "
                    "{%0,%1,%2,%3}, {%4,%5,%6,%7}, {%8,%9}, {%0,%1,%2,%3};\n"
                    : "+f"(eacc[2*np][0]), "+f"(eacc[2*np][1]),
                      "+f"(eacc[2*np][2]), "+f"(eacc[2*np][3])
                    : "r"(qf[kb][0]), "r"(qf[kb][1]), "r"(qf[kb][2]), "r"(qf[kb][3]),
                      "r"(r0), "r"(r2));
                asm volatile(
                    "mma.sync.aligned.m16n8k16.row.col.f32.f16.f16.f32 "
                    "{%0,%1,%2,%3}, {%4,%5,%6,%7}, {%8,%9}, {%0,%1,%2,%3};\n"
                    : "+f"(eacc[2*np+1][0]), "+f"(eacc[2*np+1][1]),
                      "+f"(eacc[2*np+1][2]), "+f"(eacc[2*np+1][3])
                    : "r"(qf[kb][0]), "r"(qf[kb][1]), "r"(qf[kb][2]), "r"(qf[kb][3]),
                      "r"(r1), "r"(r3));
            }
        }

        float mx0 = -1e30f, mx1 = -1e30f;
#pragma unroll
        for (int nb = 0; nb < 16; nb++) {
            int c0 = sc * 128 + nb * 8 + 2 * tq;
            if (c0 >= len)     { eacc[nb][0] = -1e9f; eacc[nb][2] = -1e9f; }
            if (c0 + 1 >= len) { eacc[nb][1] = -1e9f; eacc[nb][3] = -1e9f; }
            mx0 = fmaxf(mx0, fmaxf(eacc[nb][0], eacc[nb][1]));
            mx1 = fmaxf(mx1, fmaxf(eacc[nb][2], eacc[nb][3]));
        }
        mx0 = fmaxf(mx0, __shfl_xor_sync(0xffffffffu, mx0, 1));
        mx0 = fmaxf(mx0, __shfl_xor_sync(0xffffffffu, mx0, 2));
        mx1 = fmaxf(mx1, __shfl_xor_sync(0xffffffffu, mx1, 1));
        mx1 = fmaxf(mx1, __shfl_xor_sync(0xffffffffu, mx1, 2));

        float mn0 = fmaxf(m0, mx0), mn1 = fmaxf(m1, mx1);
        float cf0 = __expf(m0 - mn0), cf1 = __expf(m1 - mn1);
        m0 = mn0; m1 = mn1;
        l0 *= cf0; l1 *= cf1;
#pragma unroll
        for (int nb = 0; nb < 16; nb++) {
            oacc[nb][0] *= cf0; oacc[nb][1] *= cf0;
            oacc[nb][2] *= cf1; oacc[nb][3] *= cf1;
        }

        unsigned pf[16][2];
        float s0 = 0.f, s1 = 0.f;
#pragma unroll
        for (int nb = 0; nb < 16; nb++) {
            float p0 = __expf(eacc[nb][0] - m0);
            float p1 = __expf(eacc[nb][1] - m0);
            float p2 = __expf(eacc[nb][2] - m1);
            float p3 = __expf(eacc[nb][3] - m1);
            s0 += p0 + p1; s1 += p2 + p3;
            __half2 h01 = __floats2half2_rn(p0, p1);
            __half2 h23 = __floats2half2_rn(p2, p3);
            pf[nb][0] = *reinterpret_cast<unsigned*>(&h01);
            pf[nb][1] = *reinterpret_cast<unsigned*>(&h23);
        }
        s0 += __shfl_xor_sync(0xffffffffu, s0, 1);
        s0 += __shfl_xor_sync(0xffffffffu, s0, 2);
        s1 += __shfl_xor_sync(0xffffffffu, s1, 1);
        s1 += __shfl_xor_sync(0xffffffffu, s1, 2);
        l0 += s0; l1 += s1;

#pragma unroll
        for (int kb2 = 0; kb2 < 8; kb2++) {
            unsigned a0 = pf[2*kb2][0], a1 = pf[2*kb2][1];
            unsigned a2 = pf[2*kb2+1][0], a3 = pf[2*kb2+1][1];
#pragma unroll
            for (int vp = 0; vp < 8; vp++) {
                int row = kb2 * 16 + lr + (quad & 1) * 8;
                int col = vp * 16 + (quad >> 1) * 8;
                unsigned addr = (unsigned)__cvta_generic_to_shared(
                    &Vb[row * FA_LD + col]);
                unsigned r0, r1, r2, r3;
                asm volatile(
                    "ldmatrix.sync.aligned.m8n8.x4.trans.shared.b16 {%0,%1,%2,%3}, [%4];"
                    : "=r"(r0), "=r"(r1), "=r"(r2), "=r"(r3) : "r"(addr));
                asm volatile(
                    "mma.sync.aligned.m16n8k16.row.col.f32.f16.f16.f32 "
                    "{%0,%1,%2,%3}, {%4,%5,%6,%7}, {%8,%9}, {%0,%1,%2,%3};\n"
                    : "+f"(oacc[2*vp][0]), "+f"(oacc[2*vp][1]),
                      "+f"(oacc[2*vp][2]), "+f"(oacc[2*vp][3])
                    : "r"(a0), "r"(a1), "r"(a2), "r"(a3), "r"(r0), "r"(r1));
                asm volatile(
                    "mma.sync.aligned.m16n8k16.row.col.f32.f16.f16.f32 "
                    "{%0,%1,%2,%3}, {%4,%5,%6,%7}, {%8,%9}, {%0,%1,%2,%3};\n"
                    : "+f"(oacc[2*vp+1][0]), "+f"(oacc[2*vp+1][1]),
                      "+f"(oacc[2*vp+1][2]), "+f"(oacc[2*vp+1][3])
                    : "r"(a0), "r"(a1), "r"(a2), "r"(a3), "r"(r2), "r"(r3));
            }
        }

        __syncthreads();
        if (sc + 2 < 4) LOAD_KV(sc + 2, sc & 1);
    }

    float inv0 = 1.f / l0, inv1 = 1.f / l1;
    __half* orow0 = Om + (qrow0 + warp * 16 + g) * EMBEDN + KVN;
    __half* orow1 = orow0 + 8 * EMBEDN;
#pragma unroll
    for (int nb = 0; nb < 16; nb++) {
        int c = nb * 8 + 2 * tq;
        __half2 h0 = __floats2half2_rn(oacc[nb][0] * inv0, oacc[nb][1] * inv0);
        __half2 h1 = __floats2half2_rn(oacc[nb][2] * inv1, oacc[nb][3] * inv1);
        *reinterpret_cast<__half2*>(orow0 + c) = h0;
        *reinterpret_cast<__half2*>(orow1 + c) = h1;
    }
}

// ---------------- launch ----------------
extern "C" void kernel_launch(void* const* d_in, const int* in_sizes, int n_in,
                              void* d_out, int out_size)
{
    const float* key   = (const float*)d_in[0];
    const float* value = (const float*)d_in[1];
    const int*   elen  = (const int*)  d_in[2];
    const int*   y     = (const int*)  d_in[3];
    const float* E     = (const float*)d_in[4];
    const float* W1    = (const float*)d_in[5];
    const float* bi1   = (const float*)d_in[6];
    const float* bh1   = (const float*)d_in[7];
    const float* W2    = (const float*)d_in[8];
    const float* bi2   = (const float*)d_in[9];
    const float* bh2   = (const float*)d_in[10];
    const float* bout  = (const float*)d_in[11];
    float*       out   = (float*)d_out;

    float  *gates1, *gates2;
    __half *Eh, *W1h, *W2h, *keyh, *valueh, *h1h, *outctxh;
    cudaGetSymbolAddress((void**)&gates1, g_gates1);
    cudaGetSymbolAddress((void**)&gates2, g_gates2);
    cudaGetSymbolAddress((void**)&Eh,     g_Eh);
    cudaGetSymbolAddress((void**)&W1h,    g_W1h);
    cudaGetSymbolAddress((void**)&W2h,    g_W2h);
    cudaGetSymbolAddress((void**)&keyh,   g_keyh);
    cudaGetSymbolAddress((void**)&valueh, g_valueh);
    cudaGetSymbolAddress((void**)&h1h,    g_h1h);
    cudaGetSymbolAddress((void**)&outctxh,g_outctxh);

    cudaFuncSetAttribute(gemm_h<0>, cudaFuncAttributeMaxDynamicSharedMemorySize, GSMEM);
    cudaFuncSetAttribute(gemm_h<1>, cudaFuncAttributeMaxDynamicSharedMemorySize, GSMEM);
    cudaFuncSetAttribute(logits_pa, cudaFuncAttributeMaxDynamicSharedMemorySize, PA_SMEM);
    cudaFuncSetAttribute(fattn,     cudaFuncAttributeMaxDynamicSharedMemorySize, FA_SMEM);

    // 0) all fp16 conversions in one launch
    conv_all<<<CONV_TOTAL / 256, 256>>>(
        (const float4*)E, (const float4*)W1, (const float4*)W2,
        (const float4*)key, (const float4*)value,
        (uint2*)Eh, (uint2*)W1h, (uint2*)W2h, (uint2*)keyh, (uint2*)valueh);

    // 1) gates1 = embed(tokens) @ W1'^T    (M=8192, N=1536, K=256)
    gemm_h<1><<<dim3(1536 / GBN, MROWS / GBM), 256, GSMEM>>>(
        Eh, W1h, gates1, EMBEDN, EMBEDN, EMBEDN, 3 * H1N, y);

    // 2) h1 = lstm_act(gates1) -> fp16
    {
        long total = (long)MROWS * H1N;
        act_lstm<<<(unsigned)((total + 255) / 256), 256>>>(
            gates1, bi1, bh1, h1h, nullptr, H1N, 0, total);
    }

    // 3) gates2 = h1 @ W2'^T               (M=8192, N=384, K=512)
    gemm_h<0><<<dim3(384 / GBN, MROWS / GBM), 256, GSMEM>>>(
        h1h, W2h, gates2, H1N, H1N, H1N, 3 * KVN, nullptr);

    // 4) h2 = lstm_act(gates2) -> outctx[:, 0:128] only
    {
        long total = (long)MROWS * KVN;
        act_lstm<<<(unsigned)((total + 255) / 256), 256>>>(
            gates2, bi2, bh2, nullptr, outctxh, KVN, EMBEDN, total);
    }

    // 5) fused attention -> outctx[:, 128:256]
    fattn<<<dim3(TN / 64, BN_), 128, FA_SMEM>>>(
        outctxh, keyh, valueh, elen, outctxh);

    // 6) logits = E @ out_ctx^T + b_out -> out[b][v][t]
    logits_pa<<<dim3((MROWS / 128) / PA_NT, VOCABN / 128), 128, PA_SMEM>>>(
        Eh, outctxh, bout, out);

    (void)in_sizes; (void)n_in; (void)out_size;
}